// round 3
// baseline (speedup 1.0000x reference)
#include <cuda_runtime.h>
#include <cuda_bf16.h>
#include <math.h>

// ---------------------------------------------------------------------------
// VQ-VAE forward, round 2: fp32 pipeline + exact emulation of the reference's
// fp32-quantized VQ distance (dist = fl(fl(zz+ee) - fl(2*zE))).
// Shapes: B=4096, G=16384, d0=4096, d1=2048, d2=512, K(codes)=8192.
// Output layout: [loss(1)][x_recon(B*G)][q_st(B*d2)]  (fp32)
// ---------------------------------------------------------------------------

#define B_SZ   4096
#define GENE   16384
#define D0     4096
#define D1     2048
#define D2     512
#define NCODE  8192

// ---- scratch (static device globals; no allocation allowed) ----
__device__ float g_h1[(size_t)B_SZ * D0];     // 64 MB
__device__ float g_h2[(size_t)B_SZ * D1];     // 32 MB
__device__ float g_z [(size_t)B_SZ * D2];     //  8 MB
__device__ float g_S [(size_t)B_SZ * NCODE];  // 128 MB (z @ E^T)
__device__ float g_q [(size_t)B_SZ * D2];     //  8 MB (aligned copy of gathered codes)
__device__ float g_h4[(size_t)B_SZ * D1];     // 32 MB
__device__ float g_h5[(size_t)B_SZ * D0];     // 64 MB
__device__ float g_enorm[NCODE];
__device__ float g_partial[B_SZ];
__device__ int   g_idx[B_SZ];

// ---------------------------------------------------------------------------
// Generic NT GEMM:  C[m,n] = act( sum_k A[m,k] * B[n,k]  (+ bias[n]) )
// A: [M,K] row-major, B: [N,K] row-major. 128x128x16 tile, 256 threads,
// 8x8 per thread. Epilogue stores SCALAR (some C bases are odd-offset).
// ---------------------------------------------------------------------------
template<bool TANH, bool BIAS>
__global__ __launch_bounds__(256, 2)
void gemm_nt_kernel(const float* __restrict__ A, const float* __restrict__ Bm,
                    const float* __restrict__ bias, float* __restrict__ C,
                    int M, int N, int K)
{
    __shared__ float As[16][128];
    __shared__ float Bs[16][128];

    const int tid = threadIdx.x;
    const int tx  = tid & 15;   // N direction
    const int ty  = tid >> 4;   // M direction
    const int m0  = blockIdx.y * 128;
    const int n0  = blockIdx.x * 128;

    float acc[8][8];
#pragma unroll
    for (int i = 0; i < 8; i++)
#pragma unroll
        for (int j = 0; j < 8; j++) acc[i][j] = 0.0f;

    for (int k0 = 0; k0 < K; k0 += 16) {
#pragma unroll
        for (int l = 0; l < 2; l++) {
            int fi = tid * 2 + l;
            int m  = fi >> 2;
            int kq = fi & 3;
            float4 v = *reinterpret_cast<const float4*>(
                &A[(size_t)(m0 + m) * K + k0 + kq * 4]);
            As[kq * 4 + 0][m] = v.x;
            As[kq * 4 + 1][m] = v.y;
            As[kq * 4 + 2][m] = v.z;
            As[kq * 4 + 3][m] = v.w;
        }
#pragma unroll
        for (int l = 0; l < 2; l++) {
            int fi = tid * 2 + l;
            int n  = fi >> 2;
            int kq = fi & 3;
            float4 v = *reinterpret_cast<const float4*>(
                &Bm[(size_t)(n0 + n) * K + k0 + kq * 4]);
            Bs[kq * 4 + 0][n] = v.x;
            Bs[kq * 4 + 1][n] = v.y;
            Bs[kq * 4 + 2][n] = v.z;
            Bs[kq * 4 + 3][n] = v.w;
        }
        __syncthreads();

#pragma unroll
        for (int kk = 0; kk < 16; kk++) {
            float a[8], b[8];
            *reinterpret_cast<float4*>(&a[0]) = *reinterpret_cast<float4*>(&As[kk][ty * 4]);
            *reinterpret_cast<float4*>(&a[4]) = *reinterpret_cast<float4*>(&As[kk][64 + ty * 4]);
            *reinterpret_cast<float4*>(&b[0]) = *reinterpret_cast<float4*>(&Bs[kk][tx * 4]);
            *reinterpret_cast<float4*>(&b[4]) = *reinterpret_cast<float4*>(&Bs[kk][64 + tx * 4]);
#pragma unroll
            for (int i = 0; i < 8; i++)
#pragma unroll
                for (int j = 0; j < 8; j++)
                    acc[i][j] += a[i] * b[j];
        }
        __syncthreads();
    }

#pragma unroll
    for (int i = 0; i < 8; i++) {
        int m = m0 + ((i < 4) ? (ty * 4 + i) : (64 + ty * 4 + (i - 4)));
#pragma unroll
        for (int j = 0; j < 8; j++) {
            int n = n0 + ((j < 4) ? (tx * 4 + j) : (64 + tx * 4 + (j - 4)));
            float v = acc[i][j];
            if (BIAS) v += bias[n];
            if (TANH) v = tanhf(v);
            C[(size_t)m * N + n] = v;
        }
    }
}

// ---------------------------------------------------------------------------
// ||E_k||^2 per code row (plain fp32 sum)
// ---------------------------------------------------------------------------
__global__ void enorm_kernel(const float* __restrict__ E, float* __restrict__ enorm)
{
    int k = blockIdx.x;
    float s = 0.0f;
    for (int c = threadIdx.x; c < D2; c += 128) {
        float e = E[(size_t)k * D2 + c];
        s += e * e;
    }
    __shared__ float sh[128];
    sh[threadIdx.x] = s;
    __syncthreads();
    for (int off = 64; off > 0; off >>= 1) {
        if (threadIdx.x < off) sh[threadIdx.x] += sh[threadIdx.x + off];
        __syncthreads();
    }
    if (threadIdx.x == 0) enorm[k] = sh[0];
}

// ---------------------------------------------------------------------------
// Per-row argmin, EMULATING the reference's fp32 arithmetic exactly:
//   dist_k = fl( fl(zz + ee_k) - fl(2 * zE_k) ),  ties -> lowest index.
// The large zz (~50) quantizes dist to ulp(zz)~3.8e-6; ee_k (<=7.6e-6) bumps
// it by 0 or 1 quantum per code. Both effects must be reproduced; zz itself
// only needs ulp-level accuracy (grid-multiple shift invariance).
// Intrinsics (__fadd_rn etc.) prevent FMA contraction / reassociation.
// ---------------------------------------------------------------------------
__global__ void argmin_kernel(const float* __restrict__ S,
                              const float* __restrict__ enorm,
                              const float* __restrict__ z,
                              int* __restrict__ idx)
{
    int row = blockIdx.x;
    const int t = threadIdx.x;
    __shared__ float sh[256];
    __shared__ float s_zz;

    // zz = sum(z_row^2) in fp32
    {
        const float* zr = z + (size_t)row * D2;
        float a0 = zr[t];
        float a1 = zr[t + 256];
        float s = __fadd_rn(__fmul_rn(a0, a0), __fmul_rn(a1, a1));
        sh[t] = s;
        __syncthreads();
        for (int off = 128; off > 0; off >>= 1) {
            if (t < off) sh[t] = __fadd_rn(sh[t], sh[t + off]);
            __syncthreads();
        }
        if (t == 0) s_zz = sh[0];
        __syncthreads();
    }
    const float zz = s_zz;

    const float* s = S + (size_t)row * NCODE;
    float best = INFINITY;
    int   bi   = 0x7fffffff;
    for (int k = t; k < NCODE; k += 256) {
        float a = __fadd_rn(zz, enorm[k]);          // fl(zz + ee_k)
        float y = __fmul_rn(2.0f, s[k]);            // fl(2 * zE_k)
        float v = __fsub_rn(a, y);                  // fl(a - y)
        if (v < best || (v == best && k < bi)) { best = v; bi = k; }
    }
    __shared__ float sv[256];
    __shared__ int   si[256];
    sv[t] = best;
    si[t] = bi;
    __syncthreads();
    for (int off = 128; off > 0; off >>= 1) {
        if (t < off) {
            float v2 = sv[t + off];
            int   i2 = si[t + off];
            if (v2 < sv[t] || (v2 == sv[t] && i2 < si[t])) {
                sv[t] = v2;
                si[t] = i2;
            }
        }
        __syncthreads();
    }
    if (t == 0) idx[row] = si[0];
}

// ---------------------------------------------------------------------------
// Gather q = E[idx]: aligned scratch copy + q_st region of d_out.
// ---------------------------------------------------------------------------
__global__ void gather_kernel(const float* __restrict__ E,
                              const int* __restrict__ idx,
                              float* __restrict__ q_aligned,
                              float* __restrict__ q_out)
{
    int row = blockIdx.x;
    const float* src = E + (size_t)idx[row] * D2;
    float* dsta = q_aligned + (size_t)row * D2;
    float* dsto = q_out     + (size_t)row * D2;
    for (int c = threadIdx.x; c < D2; c += 128) {
        float v = src[c];
        dsta[c] = v;
        dsto[c] = v;
    }
}

// ---------------------------------------------------------------------------
// Deterministic two-stage loss: loss = 1.25 * mean((q - z)^2)
// ---------------------------------------------------------------------------
__global__ void loss_partial_kernel(const float* __restrict__ q,
                                    const float* __restrict__ z,
                                    float* __restrict__ partial)
{
    int row = blockIdx.x;
    float s = 0.0f;
    for (int c = threadIdx.x; c < D2; c += 256) {
        float d = q[(size_t)row * D2 + c] - z[(size_t)row * D2 + c];
        s += d * d;
    }
    __shared__ float sh[256];
    sh[threadIdx.x] = s;
    __syncthreads();
    for (int off = 128; off > 0; off >>= 1) {
        if (threadIdx.x < off) sh[threadIdx.x] += sh[threadIdx.x + off];
        __syncthreads();
    }
    if (threadIdx.x == 0) partial[row] = sh[0];
}

__global__ void loss_final_kernel(const float* __restrict__ partial,
                                  float* __restrict__ out)
{
    __shared__ float sh[1024];
    float s = 0.0f;
    for (int i = threadIdx.x; i < B_SZ; i += 1024) s += partial[i];
    sh[threadIdx.x] = s;
    __syncthreads();
    for (int off = 512; off > 0; off >>= 1) {
        if (threadIdx.x < off) sh[threadIdx.x] += sh[threadIdx.x + off];
        __syncthreads();
    }
    if (threadIdx.x == 0)
        out[0] = 1.25f * sh[0] / ((float)B_SZ * (float)D2);
}

// ---------------------------------------------------------------------------
// launch
// ---------------------------------------------------------------------------
extern "C" void kernel_launch(void* const* d_in, const int* in_sizes, int n_in,
                              void* d_out, int out_size)
{
    const float* X  = (const float*)d_in[0];
    const float* W1 = (const float*)d_in[1];
    const float* b1 = (const float*)d_in[2];
    const float* W2 = (const float*)d_in[3];
    const float* b2 = (const float*)d_in[4];
    const float* W3 = (const float*)d_in[5];
    const float* b3 = (const float*)d_in[6];
    const float* E  = (const float*)d_in[7];
    const float* W4 = (const float*)d_in[8];
    const float* b4 = (const float*)d_in[9];
    const float* W5 = (const float*)d_in[10];
    const float* b5 = (const float*)d_in[11];
    const float* W6 = (const float*)d_in[12];
    const float* b6 = (const float*)d_in[13];

    float* outf   = (float*)d_out;
    float* xrec   = outf + 1;                                  // [B, GENE]
    float* q_out  = outf + 1 + (size_t)B_SZ * GENE;            // [B, D2]

    float *h1, *h2, *z, *S, *q, *h4, *h5, *enorm, *partial;
    int* idx;
    cudaGetSymbolAddress((void**)&h1, g_h1);
    cudaGetSymbolAddress((void**)&h2, g_h2);
    cudaGetSymbolAddress((void**)&z,  g_z);
    cudaGetSymbolAddress((void**)&S,  g_S);
    cudaGetSymbolAddress((void**)&q,  g_q);
    cudaGetSymbolAddress((void**)&h4, g_h4);
    cudaGetSymbolAddress((void**)&h5, g_h5);
    cudaGetSymbolAddress((void**)&enorm,   g_enorm);
    cudaGetSymbolAddress((void**)&partial, g_partial);
    cudaGetSymbolAddress((void**)&idx,     g_idx);

    dim3 blk(256);

    // codebook norms (independent; launch first)
    enorm_kernel<<<NCODE, 128>>>(E, enorm);

    // encoder
    gemm_nt_kernel<true,  true ><<<dim3(D0 / 128, B_SZ / 128), blk>>>(X,  W1, b1, h1, B_SZ, D0, GENE);
    gemm_nt_kernel<true,  true ><<<dim3(D1 / 128, B_SZ / 128), blk>>>(h1, W2, b2, h2, B_SZ, D1, D0);
    gemm_nt_kernel<true,  true ><<<dim3(D2 / 128, B_SZ / 128), blk>>>(h2, W3, b3, z,  B_SZ, D2, D1);

    // VQ: scores = z @ E^T, then argmin emulating reference fp32 rounding
    gemm_nt_kernel<false, false><<<dim3(NCODE / 128, B_SZ / 128), blk>>>(z, E, (const float*)nullptr, S, B_SZ, NCODE, D2);
    argmin_kernel<<<B_SZ, 256>>>(S, enorm, z, idx);
    gather_kernel<<<B_SZ, 128>>>(E, idx, q, q_out);

    // loss = 1.25 * mean((q - z)^2), deterministic reduction
    loss_partial_kernel<<<B_SZ, 256>>>(q, z, partial);
    loss_final_kernel<<<1, 1024>>>(partial, outf);

    // decoder (q_st value == q)
    gemm_nt_kernel<true,  true ><<<dim3(D1 / 128, B_SZ / 128), blk>>>(q,  W4, b4, h4, B_SZ, D1, D2);
    gemm_nt_kernel<true,  true ><<<dim3(D0 / 128, B_SZ / 128), blk>>>(h4, W5, b5, h5, B_SZ, D0, D1);
    gemm_nt_kernel<false, true ><<<dim3(GENE / 128, B_SZ / 128), blk>>>(h5, W6, b6, xrec, B_SZ, GENE, D0);
}

// round 4
// speedup vs baseline: 1.0007x; 1.0007x over previous
#include <cuda_runtime.h>
#include <cuda_bf16.h>
#include <math.h>

// ---------------------------------------------------------------------------
// VQ-VAE forward, round 2: fp32 pipeline + exact emulation of the reference's
// fp32-quantized VQ distance (dist = fl(fl(zz+ee) - fl(2*zE))).
// Shapes: B=4096, G=16384, d0=4096, d1=2048, d2=512, K(codes)=8192.
// Output layout: [loss(1)][x_recon(B*G)][q_st(B*d2)]  (fp32)
// ---------------------------------------------------------------------------

#define B_SZ   4096
#define GENE   16384
#define D0     4096
#define D1     2048
#define D2     512
#define NCODE  8192

// ---- scratch (static device globals; no allocation allowed) ----
__device__ float g_h1[(size_t)B_SZ * D0];     // 64 MB
__device__ float g_h2[(size_t)B_SZ * D1];     // 32 MB
__device__ float g_z [(size_t)B_SZ * D2];     //  8 MB
__device__ float g_S [(size_t)B_SZ * NCODE];  // 128 MB (z @ E^T)
__device__ float g_q [(size_t)B_SZ * D2];     //  8 MB (aligned copy of gathered codes)
__device__ float g_h4[(size_t)B_SZ * D1];     // 32 MB
__device__ float g_h5[(size_t)B_SZ * D0];     // 64 MB
__device__ float g_enorm[NCODE];
__device__ float g_partial[B_SZ];
__device__ int   g_idx[B_SZ];

// ---------------------------------------------------------------------------
// Generic NT GEMM:  C[m,n] = act( sum_k A[m,k] * B[n,k]  (+ bias[n]) )
// A: [M,K] row-major, B: [N,K] row-major. 128x128x16 tile, 256 threads,
// 8x8 per thread. Epilogue stores SCALAR (some C bases are odd-offset).
// ---------------------------------------------------------------------------
template<bool TANH, bool BIAS>
__global__ __launch_bounds__(256, 2)
void gemm_nt_kernel(const float* __restrict__ A, const float* __restrict__ Bm,
                    const float* __restrict__ bias, float* __restrict__ C,
                    int M, int N, int K)
{
    __shared__ float As[16][128];
    __shared__ float Bs[16][128];

    const int tid = threadIdx.x;
    const int tx  = tid & 15;   // N direction
    const int ty  = tid >> 4;   // M direction
    const int m0  = blockIdx.y * 128;
    const int n0  = blockIdx.x * 128;

    float acc[8][8];
#pragma unroll
    for (int i = 0; i < 8; i++)
#pragma unroll
        for (int j = 0; j < 8; j++) acc[i][j] = 0.0f;

    for (int k0 = 0; k0 < K; k0 += 16) {
#pragma unroll
        for (int l = 0; l < 2; l++) {
            int fi = tid * 2 + l;
            int m  = fi >> 2;
            int kq = fi & 3;
            float4 v = *reinterpret_cast<const float4*>(
                &A[(size_t)(m0 + m) * K + k0 + kq * 4]);
            As[kq * 4 + 0][m] = v.x;
            As[kq * 4 + 1][m] = v.y;
            As[kq * 4 + 2][m] = v.z;
            As[kq * 4 + 3][m] = v.w;
        }
#pragma unroll
        for (int l = 0; l < 2; l++) {
            int fi = tid * 2 + l;
            int n  = fi >> 2;
            int kq = fi & 3;
            float4 v = *reinterpret_cast<const float4*>(
                &Bm[(size_t)(n0 + n) * K + k0 + kq * 4]);
            Bs[kq * 4 + 0][n] = v.x;
            Bs[kq * 4 + 1][n] = v.y;
            Bs[kq * 4 + 2][n] = v.z;
            Bs[kq * 4 + 3][n] = v.w;
        }
        __syncthreads();

#pragma unroll
        for (int kk = 0; kk < 16; kk++) {
            float a[8], b[8];
            *reinterpret_cast<float4*>(&a[0]) = *reinterpret_cast<float4*>(&As[kk][ty * 4]);
            *reinterpret_cast<float4*>(&a[4]) = *reinterpret_cast<float4*>(&As[kk][64 + ty * 4]);
            *reinterpret_cast<float4*>(&b[0]) = *reinterpret_cast<float4*>(&Bs[kk][tx * 4]);
            *reinterpret_cast<float4*>(&b[4]) = *reinterpret_cast<float4*>(&Bs[kk][64 + tx * 4]);
#pragma unroll
            for (int i = 0; i < 8; i++)
#pragma unroll
                for (int j = 0; j < 8; j++)
                    acc[i][j] += a[i] * b[j];
        }
        __syncthreads();
    }

#pragma unroll
    for (int i = 0; i < 8; i++) {
        int m = m0 + ((i < 4) ? (ty * 4 + i) : (64 + ty * 4 + (i - 4)));
#pragma unroll
        for (int j = 0; j < 8; j++) {
            int n = n0 + ((j < 4) ? (tx * 4 + j) : (64 + tx * 4 + (j - 4)));
            float v = acc[i][j];
            if (BIAS) v += bias[n];
            if (TANH) v = tanhf(v);
            C[(size_t)m * N + n] = v;
        }
    }
}

// ---------------------------------------------------------------------------
// ||E_k||^2 per code row (plain fp32 sum)
// ---------------------------------------------------------------------------
__global__ void enorm_kernel(const float* __restrict__ E, float* __restrict__ enorm)
{
    int k = blockIdx.x;
    float s = 0.0f;
    for (int c = threadIdx.x; c < D2; c += 128) {
        float e = E[(size_t)k * D2 + c];
        s += e * e;
    }
    __shared__ float sh[128];
    sh[threadIdx.x] = s;
    __syncthreads();
    for (int off = 64; off > 0; off >>= 1) {
        if (threadIdx.x < off) sh[threadIdx.x] += sh[threadIdx.x + off];
        __syncthreads();
    }
    if (threadIdx.x == 0) enorm[k] = sh[0];
}

// ---------------------------------------------------------------------------
// Per-row argmin, EMULATING the reference's fp32 arithmetic exactly:
//   dist_k = fl( fl(zz + ee_k) - fl(2 * zE_k) ),  ties -> lowest index.
// The large zz (~50) quantizes dist to ulp(zz)~3.8e-6; ee_k (<=7.6e-6) bumps
// it by 0 or 1 quantum per code. Both effects must be reproduced; zz itself
// only needs ulp-level accuracy (grid-multiple shift invariance).
// Intrinsics (__fadd_rn etc.) prevent FMA contraction / reassociation.
// ---------------------------------------------------------------------------
__global__ void argmin_kernel(const float* __restrict__ S,
                              const float* __restrict__ enorm,
                              const float* __restrict__ z,
                              int* __restrict__ idx)
{
    int row = blockIdx.x;
    const int t = threadIdx.x;
    __shared__ float sh[256];
    __shared__ float s_zz;

    // zz = sum(z_row^2) in fp32
    {
        const float* zr = z + (size_t)row * D2;
        float a0 = zr[t];
        float a1 = zr[t + 256];
        float s = __fadd_rn(__fmul_rn(a0, a0), __fmul_rn(a1, a1));
        sh[t] = s;
        __syncthreads();
        for (int off = 128; off > 0; off >>= 1) {
            if (t < off) sh[t] = __fadd_rn(sh[t], sh[t + off]);
            __syncthreads();
        }
        if (t == 0) s_zz = sh[0];
        __syncthreads();
    }
    const float zz = s_zz;

    const float* s = S + (size_t)row * NCODE;
    float best = INFINITY;
    int   bi   = 0x7fffffff;
    for (int k = t; k < NCODE; k += 256) {
        float a = __fadd_rn(zz, enorm[k]);          // fl(zz + ee_k)
        float y = __fmul_rn(2.0f, s[k]);            // fl(2 * zE_k)
        float v = __fsub_rn(a, y);                  // fl(a - y)
        if (v < best || (v == best && k < bi)) { best = v; bi = k; }
    }
    __shared__ float sv[256];
    __shared__ int   si[256];
    sv[t] = best;
    si[t] = bi;
    __syncthreads();
    for (int off = 128; off > 0; off >>= 1) {
        if (t < off) {
            float v2 = sv[t + off];
            int   i2 = si[t + off];
            if (v2 < sv[t] || (v2 == sv[t] && i2 < si[t])) {
                sv[t] = v2;
                si[t] = i2;
            }
        }
        __syncthreads();
    }
    if (t == 0) idx[row] = si[0];
}

// ---------------------------------------------------------------------------
// Gather q = E[idx]: aligned scratch copy + q_st region of d_out.
// ---------------------------------------------------------------------------
__global__ void gather_kernel(const float* __restrict__ E,
                              const int* __restrict__ idx,
                              float* __restrict__ q_aligned,
                              float* __restrict__ q_out)
{
    int row = blockIdx.x;
    const float* src = E + (size_t)idx[row] * D2;
    float* dsta = q_aligned + (size_t)row * D2;
    float* dsto = q_out     + (size_t)row * D2;
    for (int c = threadIdx.x; c < D2; c += 128) {
        float v = src[c];
        dsta[c] = v;
        dsto[c] = v;
    }
}

// ---------------------------------------------------------------------------
// Deterministic two-stage loss: loss = 1.25 * mean((q - z)^2)
// ---------------------------------------------------------------------------
__global__ void loss_partial_kernel(const float* __restrict__ q,
                                    const float* __restrict__ z,
                                    float* __restrict__ partial)
{
    int row = blockIdx.x;
    float s = 0.0f;
    for (int c = threadIdx.x; c < D2; c += 256) {
        float d = q[(size_t)row * D2 + c] - z[(size_t)row * D2 + c];
        s += d * d;
    }
    __shared__ float sh[256];
    sh[threadIdx.x] = s;
    __syncthreads();
    for (int off = 128; off > 0; off >>= 1) {
        if (threadIdx.x < off) sh[threadIdx.x] += sh[threadIdx.x + off];
        __syncthreads();
    }
    if (threadIdx.x == 0) partial[row] = sh[0];
}

__global__ void loss_final_kernel(const float* __restrict__ partial,
                                  float* __restrict__ out)
{
    __shared__ float sh[1024];
    float s = 0.0f;
    for (int i = threadIdx.x; i < B_SZ; i += 1024) s += partial[i];
    sh[threadIdx.x] = s;
    __syncthreads();
    for (int off = 512; off > 0; off >>= 1) {
        if (threadIdx.x < off) sh[threadIdx.x] += sh[threadIdx.x + off];
        __syncthreads();
    }
    if (threadIdx.x == 0)
        out[0] = 1.25f * sh[0] / ((float)B_SZ * (float)D2);
}

// ---------------------------------------------------------------------------
// launch
// ---------------------------------------------------------------------------
extern "C" void kernel_launch(void* const* d_in, const int* in_sizes, int n_in,
                              void* d_out, int out_size)
{
    const float* X  = (const float*)d_in[0];
    const float* W1 = (const float*)d_in[1];
    const float* b1 = (const float*)d_in[2];
    const float* W2 = (const float*)d_in[3];
    const float* b2 = (const float*)d_in[4];
    const float* W3 = (const float*)d_in[5];
    const float* b3 = (const float*)d_in[6];
    const float* E  = (const float*)d_in[7];
    const float* W4 = (const float*)d_in[8];
    const float* b4 = (const float*)d_in[9];
    const float* W5 = (const float*)d_in[10];
    const float* b5 = (const float*)d_in[11];
    const float* W6 = (const float*)d_in[12];
    const float* b6 = (const float*)d_in[13];

    float* outf   = (float*)d_out;
    float* xrec   = outf + 1;                                  // [B, GENE]
    float* q_out  = outf + 1 + (size_t)B_SZ * GENE;            // [B, D2]

    float *h1, *h2, *z, *S, *q, *h4, *h5, *enorm, *partial;
    int* idx;
    cudaGetSymbolAddress((void**)&h1, g_h1);
    cudaGetSymbolAddress((void**)&h2, g_h2);
    cudaGetSymbolAddress((void**)&z,  g_z);
    cudaGetSymbolAddress((void**)&S,  g_S);
    cudaGetSymbolAddress((void**)&q,  g_q);
    cudaGetSymbolAddress((void**)&h4, g_h4);
    cudaGetSymbolAddress((void**)&h5, g_h5);
    cudaGetSymbolAddress((void**)&enorm,   g_enorm);
    cudaGetSymbolAddress((void**)&partial, g_partial);
    cudaGetSymbolAddress((void**)&idx,     g_idx);

    dim3 blk(256);

    // codebook norms (independent; launch first)
    enorm_kernel<<<NCODE, 128>>>(E, enorm);

    // encoder
    gemm_nt_kernel<true,  true ><<<dim3(D0 / 128, B_SZ / 128), blk>>>(X,  W1, b1, h1, B_SZ, D0, GENE);
    gemm_nt_kernel<true,  true ><<<dim3(D1 / 128, B_SZ / 128), blk>>>(h1, W2, b2, h2, B_SZ, D1, D0);
    gemm_nt_kernel<true,  true ><<<dim3(D2 / 128, B_SZ / 128), blk>>>(h2, W3, b3, z,  B_SZ, D2, D1);

    // VQ: scores = z @ E^T, then argmin emulating reference fp32 rounding
    gemm_nt_kernel<false, false><<<dim3(NCODE / 128, B_SZ / 128), blk>>>(z, E, (const float*)nullptr, S, B_SZ, NCODE, D2);
    argmin_kernel<<<B_SZ, 256>>>(S, enorm, z, idx);
    gather_kernel<<<B_SZ, 128>>>(E, idx, q, q_out);

    // loss = 1.25 * mean((q - z)^2), deterministic reduction
    loss_partial_kernel<<<B_SZ, 256>>>(q, z, partial);
    loss_final_kernel<<<1, 1024>>>(partial, outf);

    // decoder (q_st value == q)
    gemm_nt_kernel<true,  true ><<<dim3(D1 / 128, B_SZ / 128), blk>>>(q,  W4, b4, h4, B_SZ, D1, D2);
    gemm_nt_kernel<true,  true ><<<dim3(D0 / 128, B_SZ / 128), blk>>>(h4, W5, b5, h5, B_SZ, D0, D1);
    gemm_nt_kernel<false, true ><<<dim3(GENE / 128, B_SZ / 128), blk>>>(h5, W6, b6, xrec, B_SZ, GENE, D0);
}

// round 9
// speedup vs baseline: 1.3507x; 1.3497x over previous
#include <cuda_runtime.h>
#include <cuda_bf16.h>
#include <cstdint>
#include <math.h>

// ---------------------------------------------------------------------------
// VQ-VAE forward, round 8:
//   encoder G1,G2 : 3-way bf16 split, 6 MMA products, PER-K-STEP accumulator
//                   flush into RN fp32 sums (defeats HMMA RZ-accum bias)
//   decoder G4-G6 : 2-way bf16 split, 3 MMA products, plain HMMA accumulation
//   VQ-critical   : fp32 SIMT (G3, z@E^T, fp32-rounding-emulated argmin)
// Output layout: [loss(1)][x_recon(B*G)][q_st(B*d2)]  (fp32)
// ---------------------------------------------------------------------------

#define B_SZ   4096
#define GENE   16384
#define D0     4096
#define D1     2048
#define D2     512
#define NCODE  8192

// ============================ scratch =====================================
__device__ __align__(16) __nv_bfloat16 g_Xh [(size_t)B_SZ * GENE];
__device__ __align__(16) __nv_bfloat16 g_Xm [(size_t)B_SZ * GENE];
__device__ __align__(16) __nv_bfloat16 g_Xl [(size_t)B_SZ * GENE];
__device__ __align__(16) __nv_bfloat16 g_W1h[(size_t)D0 * GENE];
__device__ __align__(16) __nv_bfloat16 g_W1m[(size_t)D0 * GENE];
__device__ __align__(16) __nv_bfloat16 g_W1l[(size_t)D0 * GENE];
__device__ __align__(16) __nv_bfloat16 g_h1h[(size_t)B_SZ * D0];
__device__ __align__(16) __nv_bfloat16 g_h1m[(size_t)B_SZ * D0];
__device__ __align__(16) __nv_bfloat16 g_h1l[(size_t)B_SZ * D0];
__device__ __align__(16) __nv_bfloat16 g_W2h[(size_t)D1 * D0];
__device__ __align__(16) __nv_bfloat16 g_W2m[(size_t)D1 * D0];
__device__ __align__(16) __nv_bfloat16 g_W2l[(size_t)D1 * D0];
__device__ __align__(16) __nv_bfloat16 g_W4h[(size_t)D1 * D2];
__device__ __align__(16) __nv_bfloat16 g_W4l[(size_t)D1 * D2];
__device__ __align__(16) __nv_bfloat16 g_qh [(size_t)B_SZ * D2];
__device__ __align__(16) __nv_bfloat16 g_ql [(size_t)B_SZ * D2];
__device__ __align__(16) __nv_bfloat16 g_h4h[(size_t)B_SZ * D1];
__device__ __align__(16) __nv_bfloat16 g_h4l[(size_t)B_SZ * D1];
__device__ __align__(16) __nv_bfloat16 g_W5h[(size_t)D0 * D1];
__device__ __align__(16) __nv_bfloat16 g_W5l[(size_t)D0 * D1];
__device__ __align__(16) __nv_bfloat16 g_h5h[(size_t)B_SZ * D0];
__device__ __align__(16) __nv_bfloat16 g_h5l[(size_t)B_SZ * D0];
__device__ __align__(16) __nv_bfloat16 g_W6h[(size_t)GENE * D0];
__device__ __align__(16) __nv_bfloat16 g_W6l[(size_t)GENE * D0];
__device__ float g_h2f[(size_t)B_SZ * D1];
__device__ float g_z  [(size_t)B_SZ * D2];
__device__ float g_S  [(size_t)B_SZ * NCODE];
__device__ float g_q  [(size_t)B_SZ * D2];
__device__ float g_enorm[NCODE];
__device__ float g_partial[B_SZ];
__device__ int   g_idx[B_SZ];

// ====================== fp32 -> bf16 splits ===============================
__global__ void split2_kernel(const float4* __restrict__ src,
                              __nv_bfloat162* __restrict__ hi,
                              __nv_bfloat162* __restrict__ lo, int n4)
{
    for (int i = blockIdx.x * blockDim.x + threadIdx.x; i < n4;
         i += gridDim.x * blockDim.x) {
        float4 v = src[i];
        float f[4] = { v.x, v.y, v.z, v.w };
        __nv_bfloat16 H[4], L[4];
#pragma unroll
        for (int j = 0; j < 4; j++) {
            H[j] = __float2bfloat16(f[j]);
            L[j] = __float2bfloat16(f[j] - __bfloat162float(H[j]));
        }
        hi[2 * i]     = __nv_bfloat162(H[0], H[1]);
        hi[2 * i + 1] = __nv_bfloat162(H[2], H[3]);
        lo[2 * i]     = __nv_bfloat162(L[0], L[1]);
        lo[2 * i + 1] = __nv_bfloat162(L[2], L[3]);
    }
}

__global__ void split3_kernel(const float4* __restrict__ src,
                              __nv_bfloat162* __restrict__ hi,
                              __nv_bfloat162* __restrict__ mid,
                              __nv_bfloat162* __restrict__ lo, int n4)
{
    for (int i = blockIdx.x * blockDim.x + threadIdx.x; i < n4;
         i += gridDim.x * blockDim.x) {
        float4 v = src[i];
        float f[4] = { v.x, v.y, v.z, v.w };
        __nv_bfloat16 H[4], Mv[4], L[4];
#pragma unroll
        for (int j = 0; j < 4; j++) {
            H[j] = __float2bfloat16(f[j]);
            float r = f[j] - __bfloat162float(H[j]);
            Mv[j] = __float2bfloat16(r);
            L[j]  = __float2bfloat16(r - __bfloat162float(Mv[j]));
        }
        hi [2 * i]     = __nv_bfloat162(H[0], H[1]);
        hi [2 * i + 1] = __nv_bfloat162(H[2], H[3]);
        mid[2 * i]     = __nv_bfloat162(Mv[0], Mv[1]);
        mid[2 * i + 1] = __nv_bfloat162(Mv[2], Mv[3]);
        lo [2 * i]     = __nv_bfloat162(L[0], L[1]);
        lo [2 * i + 1] = __nv_bfloat162(L[2], L[3]);
    }
}

// ===================== mma.sync common pieces =============================
#define ROW_B    80
#define MAT_B    (128 * ROW_B)

__device__ __forceinline__ uint32_t smem_u32(const void* p) {
    uint32_t a;
    asm("{ .reg .u64 t; cvta.to.shared.u64 t, %1; cvt.u32.u64 %0, t; }"
        : "=r"(a) : "l"(p));
    return a;
}
__device__ __forceinline__ void ldmx4(uint32_t* r, uint32_t addr) {
    asm volatile("ldmatrix.sync.aligned.m8n8.x4.shared.b16 {%0,%1,%2,%3}, [%4];"
        : "=r"(r[0]), "=r"(r[1]), "=r"(r[2]), "=r"(r[3]) : "r"(addr));
}
__device__ __forceinline__ void mma16816(float* d, const uint32_t* a,
                                         uint32_t b0, uint32_t b1) {
    asm volatile(
        "mma.sync.aligned.m16n8k16.row.col.f32.bf16.bf16.f32 "
        "{%0,%1,%2,%3}, {%4,%5,%6,%7}, {%8,%9}, {%0,%1,%2,%3};"
        : "+f"(d[0]), "+f"(d[1]), "+f"(d[2]), "+f"(d[3])
        : "r"(a[0]), "r"(a[1]), "r"(a[2]), "r"(a[3]), "r"(b0), "r"(b1));
}

template<int NMAT>
__device__ __forceinline__ void load_stage_n(
    uint32_t st, const __nv_bfloat16* const* bases, int K, int k0, int tid)
{
#pragma unroll
    for (int i = 0; i < 2 * NMAT; i++) {
        int c   = tid + i * 256;
        int mat = c >> 9;
        int r   = (c & 511) >> 2;
        int ch  = c & 3;
        uint32_t dst = st + mat * MAT_B + r * ROW_B + ch * 16;
        const char* src = (const char*)bases[mat] + ((size_t)k0 + (size_t)r * K + ch * 8) * 2;
        asm volatile("cp.async.cg.shared.global [%0], [%1], 16;"
                     :: "r"(dst), "l"(src) : "memory");
    }
}

// ============ 2-way split GEMM (decoder): 3 products, 4 stages ============
#define STAGE2_B  (4 * MAT_B)
#define NSTAGE2   4
#define SMEM_MMA2 (NSTAGE2 * STAGE2_B)

template<bool TANH, bool WRITE_SPLIT, bool WRITE_F32>
__global__ __launch_bounds__(256, 1)
void gemm_mma2_kernel(const __nv_bfloat16* __restrict__ Ahi, const __nv_bfloat16* __restrict__ Alo,
                      const __nv_bfloat16* __restrict__ Bhi, const __nv_bfloat16* __restrict__ Blo,
                      const float* __restrict__ bias,
                      __nv_bfloat16* __restrict__ Chi, __nv_bfloat16* __restrict__ Clo,
                      float* __restrict__ Cf,
                      int M, int N, int K)
{
    extern __shared__ char smem[];
    const uint32_t sb = smem_u32(smem);
    const int tid = threadIdx.x;
    const int wid = tid >> 5;
    const int lid = tid & 31;
    const int wm  = wid >> 2;
    const int wn  = wid & 3;
    const int m0  = blockIdx.y * 128;
    const int n0  = blockIdx.x * 128;

    const __nv_bfloat16* bases[4] = {
        Ahi + (size_t)m0 * K, Alo + (size_t)m0 * K,
        Bhi + (size_t)n0 * K, Blo + (size_t)n0 * K };

    float acc[4][4][4];
#pragma unroll
    for (int i = 0; i < 4; i++)
#pragma unroll
        for (int j = 0; j < 4; j++)
#pragma unroll
            for (int v = 0; v < 4; v++) acc[i][j][v] = 0.0f;

    const int KT = K >> 5;
#pragma unroll
    for (int s = 0; s < NSTAGE2 - 1; s++) {
        if (s < KT) load_stage_n<4>(sb + s * STAGE2_B, bases, K, s << 5, tid);
        asm volatile("cp.async.commit_group;" ::: "memory");
    }

    const int lrow  = lid & 15;
    const int lhalf = lid >> 4;

    for (int kt = 0; kt < KT; kt++) {
        asm volatile("cp.async.wait_group %0;" :: "n"(NSTAGE2 - 2) : "memory");
        __syncthreads();

        const uint32_t st = sb + (kt % NSTAGE2) * STAGE2_B;
        const uint32_t a_base = st + (wm * 64 + lrow) * ROW_B + lhalf * 16;
        const uint32_t b_base = st + 2 * MAT_B + (wn * 32 + lrow) * ROW_B + lhalf * 16;

#pragma unroll
        for (int ks = 0; ks < 2; ks++) {
            uint32_t ah[4][4], al[4][4], bh[2][4], bl[2][4];
#pragma unroll
            for (int mi = 0; mi < 4; mi++) {
                ldmx4(ah[mi], a_base + mi * (16 * ROW_B) + ks * 32);
                ldmx4(al[mi], a_base + MAT_B + mi * (16 * ROW_B) + ks * 32);
            }
#pragma unroll
            for (int nj = 0; nj < 2; nj++) {
                ldmx4(bh[nj], b_base + nj * (16 * ROW_B) + ks * 32);
                ldmx4(bl[nj], b_base + MAT_B + nj * (16 * ROW_B) + ks * 32);
            }
#pragma unroll
            for (int mi = 0; mi < 4; mi++)
#pragma unroll
                for (int nj = 0; nj < 2; nj++)
#pragma unroll
                    for (int s = 0; s < 2; s++) {
                        float* d = acc[mi][nj * 2 + s];
                        mma16816(d, ah[mi], bh[nj][s], bh[nj][s + 2]);
                        mma16816(d, al[mi], bh[nj][s], bh[nj][s + 2]);
                        mma16816(d, ah[mi], bl[nj][s], bl[nj][s + 2]);
                    }
        }
        __syncthreads();

        const int nk = kt + NSTAGE2 - 1;
        if (nk < KT)
            load_stage_n<4>(sb + (nk % NSTAGE2) * STAGE2_B, bases, K, nk << 5, tid);
        asm volatile("cp.async.commit_group;" ::: "memory");
    }

    const int tr = lid >> 2;
    const int tc = (lid & 3) * 2;
#pragma unroll
    for (int mi = 0; mi < 4; mi++) {
#pragma unroll
        for (int nn = 0; nn < 4; nn++) {
            int n  = n0 + wn * 32 + nn * 8 + tc;
            float bv0 = bias[n], bv1 = bias[n + 1];
#pragma unroll
            for (int half = 0; half < 2; half++) {
                int m = m0 + wm * 64 + mi * 16 + tr + half * 8;
                float v0 = acc[mi][nn][half * 2 + 0] + bv0;
                float v1 = acc[mi][nn][half * 2 + 1] + bv1;
                if (TANH) { v0 = tanhf(v0); v1 = tanhf(v1); }
                size_t o = (size_t)m * N + n;
                if (WRITE_SPLIT) {
                    __nv_bfloat16 h0 = __float2bfloat16(v0);
                    __nv_bfloat16 h1 = __float2bfloat16(v1);
                    Chi[o]     = h0;
                    Chi[o + 1] = h1;
                    Clo[o]     = __float2bfloat16(v0 - __bfloat162float(h0));
                    Clo[o + 1] = __float2bfloat16(v1 - __bfloat162float(h1));
                }
                if (WRITE_F32) { Cf[o] = v0; Cf[o + 1] = v1; }
            }
        }
    }
}

// ===== 3-way split GEMM (encoder): 6 products, PER-K-STEP FLUSH ==========
// Each k=16 step: 6 MMAs into a zeroed temp accumulator, then RN fp32 adds
// into persistent sums. Kills the HMMA RZ-accumulation bias (random-walk
// cancellation instead of linear drift) -> z error ~1e-7 level.
#define STAGE3_B  (6 * MAT_B)
#define NSTAGE3   3
#define SMEM_MMA3 (NSTAGE3 * STAGE3_B)

template<bool WRITE_SPLIT3, bool WRITE_F32>
__global__ __launch_bounds__(256, 1)
void gemm_mma3_kernel(const __nv_bfloat16* __restrict__ Ahi, const __nv_bfloat16* __restrict__ Amd,
                      const __nv_bfloat16* __restrict__ Alo,
                      const __nv_bfloat16* __restrict__ Bhi, const __nv_bfloat16* __restrict__ Bmd,
                      const __nv_bfloat16* __restrict__ Blo,
                      const float* __restrict__ bias,
                      __nv_bfloat16* __restrict__ Chi, __nv_bfloat16* __restrict__ Cmd,
                      __nv_bfloat16* __restrict__ Clo,
                      float* __restrict__ Cf,
                      int M, int N, int K)
{
    extern __shared__ char smem[];
    const uint32_t sb = smem_u32(smem);
    const int tid = threadIdx.x;
    const int wid = tid >> 5;
    const int lid = tid & 31;
    const int wm  = wid >> 2;
    const int wn  = wid & 3;
    const int m0  = blockIdx.y * 128;
    const int n0  = blockIdx.x * 128;

    const __nv_bfloat16* bases[6] = {
        Ahi + (size_t)m0 * K, Amd + (size_t)m0 * K, Alo + (size_t)m0 * K,
        Bhi + (size_t)n0 * K, Bmd + (size_t)n0 * K, Blo + (size_t)n0 * K };

    float acc[4][4][4];
#pragma unroll
    for (int i = 0; i < 4; i++)
#pragma unroll
        for (int j = 0; j < 4; j++)
#pragma unroll
            for (int v = 0; v < 4; v++) acc[i][j][v] = 0.0f;

    const int KT = K >> 5;
#pragma unroll
    for (int s = 0; s < NSTAGE3 - 1; s++) {
        if (s < KT) load_stage_n<6>(sb + s * STAGE3_B, bases, K, s << 5, tid);
        asm volatile("cp.async.commit_group;" ::: "memory");
    }

    const int lrow  = lid & 15;
    const int lhalf = lid >> 4;

    for (int kt = 0; kt < KT; kt++) {
        asm volatile("cp.async.wait_group %0;" :: "n"(NSTAGE3 - 2) : "memory");
        __syncthreads();

        const uint32_t st = sb + (kt % NSTAGE3) * STAGE3_B;
        const uint32_t a_base = st + (wm * 64 + lrow) * ROW_B + lhalf * 16;
        const uint32_t b_base = st + 3 * MAT_B + (wn * 32 + lrow) * ROW_B + lhalf * 16;

#pragma unroll
        for (int ks = 0; ks < 2; ks++) {
            uint32_t bh[2][4], bm[2][4], bl[2][4];
#pragma unroll
            for (int nj = 0; nj < 2; nj++) {
                ldmx4(bh[nj], b_base + nj * (16 * ROW_B) + ks * 32);
                ldmx4(bm[nj], b_base + MAT_B + nj * (16 * ROW_B) + ks * 32);
                ldmx4(bl[nj], b_base + 2 * MAT_B + nj * (16 * ROW_B) + ks * 32);
            }
#pragma unroll
            for (int mi = 0; mi < 4; mi++) {
                uint32_t ah[4], am[4], al[4];
                ldmx4(ah, a_base + mi * (16 * ROW_B) + ks * 32);
                ldmx4(am, a_base + MAT_B + mi * (16 * ROW_B) + ks * 32);
                ldmx4(al, a_base + 2 * MAT_B + mi * (16 * ROW_B) + ks * 32);
#pragma unroll
                for (int nj = 0; nj < 2; nj++)
#pragma unroll
                    for (int s = 0; s < 2; s++) {
                        uint32_t h0 = bh[nj][s], h1 = bh[nj][s + 2];
                        uint32_t mm0 = bm[nj][s], mm1 = bm[nj][s + 2];
                        float t4[4] = {0.0f, 0.0f, 0.0f, 0.0f};
                        mma16816(t4, ah, h0, h1);                       // HH
                        mma16816(t4, am, h0, h1);                       // MH
                        mma16816(t4, ah, mm0, mm1);                     // HM
                        mma16816(t4, am, mm0, mm1);                     // MM
                        mma16816(t4, al, h0, h1);                       // LH
                        mma16816(t4, ah, bl[nj][s], bl[nj][s + 2]);     // HL
                        float* d = acc[mi][nj * 2 + s];
                        d[0] = __fadd_rn(d[0], t4[0]);
                        d[1] = __fadd_rn(d[1], t4[1]);
                        d[2] = __fadd_rn(d[2], t4[2]);
                        d[3] = __fadd_rn(d[3], t4[3]);
                    }
            }
        }
        __syncthreads();

        const int nk = kt + NSTAGE3 - 1;
        if (nk < KT)
            load_stage_n<6>(sb + (nk % NSTAGE3) * STAGE3_B, bases, K, nk << 5, tid);
        asm volatile("cp.async.commit_group;" ::: "memory");
    }

    const int tr = lid >> 2;
    const int tc = (lid & 3) * 2;
#pragma unroll
    for (int mi = 0; mi < 4; mi++) {
#pragma unroll
        for (int nn = 0; nn < 4; nn++) {
            int n  = n0 + wn * 32 + nn * 8 + tc;
            float bv0 = bias[n], bv1 = bias[n + 1];
#pragma unroll
            for (int half = 0; half < 2; half++) {
                int m = m0 + wm * 64 + mi * 16 + tr + half * 8;
                float v0 = tanhf(acc[mi][nn][half * 2 + 0] + bv0);
                float v1 = tanhf(acc[mi][nn][half * 2 + 1] + bv1);
                size_t o = (size_t)m * N + n;
                if (WRITE_SPLIT3) {
                    __nv_bfloat16 h0 = __float2bfloat16(v0);
                    float r0 = v0 - __bfloat162float(h0);
                    __nv_bfloat16 m0b = __float2bfloat16(r0);
                    __nv_bfloat16 h1 = __float2bfloat16(v1);
                    float r1 = v1 - __bfloat162float(h1);
                    __nv_bfloat16 m1b = __float2bfloat16(r1);
                    Chi[o]     = h0;  Chi[o + 1] = h1;
                    Cmd[o]     = m0b; Cmd[o + 1] = m1b;
                    Clo[o]     = __float2bfloat16(r0 - __bfloat162float(m0b));
                    Clo[o + 1] = __float2bfloat16(r1 - __bfloat162float(m1b));
                }
                if (WRITE_F32) { Cf[o] = v0; Cf[o + 1] = v1; }
            }
        }
    }
}

// ===================== fp32 SIMT GEMM (VQ-critical path) ==================
template<bool TANH, bool BIAS>
__global__ __launch_bounds__(256, 2)
void gemm_nt_kernel(const float* __restrict__ A, const float* __restrict__ Bm,
                    const float* __restrict__ bias, float* __restrict__ C,
                    int M, int N, int K)
{
    __shared__ float As[16][128];
    __shared__ float Bs[16][128];
    const int tid = threadIdx.x;
    const int tx  = tid & 15;
    const int ty  = tid >> 4;
    const int m0  = blockIdx.y * 128;
    const int n0  = blockIdx.x * 128;

    float acc[8][8];
#pragma unroll
    for (int i = 0; i < 8; i++)
#pragma unroll
        for (int j = 0; j < 8; j++) acc[i][j] = 0.0f;

    for (int k0 = 0; k0 < K; k0 += 16) {
#pragma unroll
        for (int l = 0; l < 2; l++) {
            int fi = tid * 2 + l;
            int m = fi >> 2, kq = fi & 3;
            float4 v = *reinterpret_cast<const float4*>(&A[(size_t)(m0 + m) * K + k0 + kq * 4]);
            As[kq * 4 + 0][m] = v.x; As[kq * 4 + 1][m] = v.y;
            As[kq * 4 + 2][m] = v.z; As[kq * 4 + 3][m] = v.w;
        }
#pragma unroll
        for (int l = 0; l < 2; l++) {
            int fi = tid * 2 + l;
            int n = fi >> 2, kq = fi & 3;
            float4 v = *reinterpret_cast<const float4*>(&Bm[(size_t)(n0 + n) * K + k0 + kq * 4]);
            Bs[kq * 4 + 0][n] = v.x; Bs[kq * 4 + 1][n] = v.y;
            Bs[kq * 4 + 2][n] = v.z; Bs[kq * 4 + 3][n] = v.w;
        }
        __syncthreads();
#pragma unroll
        for (int kk = 0; kk < 16; kk++) {
            float a[8], b[8];
            *reinterpret_cast<float4*>(&a[0]) = *reinterpret_cast<float4*>(&As[kk][ty * 4]);
            *reinterpret_cast<float4*>(&a[4]) = *reinterpret_cast<float4*>(&As[kk][64 + ty * 4]);
            *reinterpret_cast<float4*>(&b[0]) = *reinterpret_cast<float4*>(&Bs[kk][tx * 4]);
            *reinterpret_cast<float4*>(&b[4]) = *reinterpret_cast<float4*>(&Bs[kk][64 + tx * 4]);
#pragma unroll
            for (int i = 0; i < 8; i++)
#pragma unroll
                for (int j = 0; j < 8; j++) acc[i][j] += a[i] * b[j];
        }
        __syncthreads();
    }
#pragma unroll
    for (int i = 0; i < 8; i++) {
        int m = m0 + ((i < 4) ? (ty * 4 + i) : (64 + ty * 4 + (i - 4)));
#pragma unroll
        for (int j = 0; j < 8; j++) {
            int n = n0 + ((j < 4) ? (tx * 4 + j) : (64 + tx * 4 + (j - 4)));
            float v = acc[i][j];
            if (BIAS) v += bias[n];
            if (TANH) v = tanhf(v);
            C[(size_t)m * N + n] = v;
        }
    }
}

// =========================== VQ helpers ===================================
__global__ void enorm_kernel(const float* __restrict__ E, float* __restrict__ enorm)
{
    int k = blockIdx.x;
    float s = 0.0f;
    for (int c = threadIdx.x; c < D2; c += 128) {
        float e = E[(size_t)k * D2 + c];
        s += e * e;
    }
    __shared__ float sh[128];
    sh[threadIdx.x] = s;
    __syncthreads();
    for (int off = 64; off > 0; off >>= 1) {
        if (threadIdx.x < off) sh[threadIdx.x] += sh[threadIdx.x + off];
        __syncthreads();
    }
    if (threadIdx.x == 0) enorm[k] = sh[0];
}

__global__ void argmin_kernel(const float* __restrict__ S,
                              const float* __restrict__ enorm,
                              const float* __restrict__ z,
                              int* __restrict__ idx)
{
    int row = blockIdx.x;
    const int t = threadIdx.x;
    __shared__ float sh[256];
    __shared__ float s_zz;
    {
        const float* zr = z + (size_t)row * D2;
        float a0 = zr[t], a1 = zr[t + 256];
        sh[t] = __fadd_rn(__fmul_rn(a0, a0), __fmul_rn(a1, a1));
        __syncthreads();
        for (int off = 128; off > 0; off >>= 1) {
            if (t < off) sh[t] = __fadd_rn(sh[t], sh[t + off]);
            __syncthreads();
        }
        if (t == 0) s_zz = sh[0];
        __syncthreads();
    }
    const float zz = s_zz;
    const float* s = S + (size_t)row * NCODE;
    float best = INFINITY;
    int   bi   = 0x7fffffff;
    for (int k = t; k < NCODE; k += 256) {
        float a = __fadd_rn(zz, enorm[k]);
        float y = __fmul_rn(2.0f, s[k]);
        float v = __fsub_rn(a, y);
        if (v < best || (v == best && k < bi)) { best = v; bi = k; }
    }
    __shared__ float sv[256];
    __shared__ int   si[256];
    sv[t] = best; si[t] = bi;
    __syncthreads();
    for (int off = 128; off > 0; off >>= 1) {
        if (t < off) {
            float v2 = sv[t + off]; int i2 = si[t + off];
            if (v2 < sv[t] || (v2 == sv[t] && i2 < si[t])) { sv[t] = v2; si[t] = i2; }
        }
        __syncthreads();
    }
    if (t == 0) idx[row] = si[0];
}

__global__ void gather_kernel(const float* __restrict__ E, const int* __restrict__ idx,
                              float* __restrict__ q_aligned, float* __restrict__ q_out,
                              __nv_bfloat16* __restrict__ qh, __nv_bfloat16* __restrict__ ql)
{
    int row = blockIdx.x;
    const float* src = E + (size_t)idx[row] * D2;
    size_t off = (size_t)row * D2;
    for (int c = threadIdx.x; c < D2; c += 128) {
        float v = src[c];
        q_aligned[off + c] = v;
        q_out[off + c]     = v;
        __nv_bfloat16 h = __float2bfloat16(v);
        qh[off + c] = h;
        ql[off + c] = __float2bfloat16(v - __bfloat162float(h));
    }
}

__global__ void loss_partial_kernel(const float* __restrict__ q, const float* __restrict__ z,
                                    float* __restrict__ partial)
{
    int row = blockIdx.x;
    float s = 0.0f;
    for (int c = threadIdx.x; c < D2; c += 256) {
        float d = q[(size_t)row * D2 + c] - z[(size_t)row * D2 + c];
        s += d * d;
    }
    __shared__ float sh[256];
    sh[threadIdx.x] = s;
    __syncthreads();
    for (int off = 128; off > 0; off >>= 1) {
        if (threadIdx.x < off) sh[threadIdx.x] += sh[threadIdx.x + off];
        __syncthreads();
    }
    if (threadIdx.x == 0) partial[row] = sh[0];
}

__global__ void loss_final_kernel(const float* __restrict__ partial, float* __restrict__ out)
{
    __shared__ float sh[1024];
    float s = 0.0f;
    for (int i = threadIdx.x; i < B_SZ; i += 1024) s += partial[i];
    sh[threadIdx.x] = s;
    __syncthreads();
    for (int off = 512; off > 0; off >>= 1) {
        if (threadIdx.x < off) sh[threadIdx.x] += sh[threadIdx.x + off];
        __syncthreads();
    }
    if (threadIdx.x == 0) out[0] = 1.25f * sh[0] / ((float)B_SZ * (float)D2);
}

// =============================== launch ===================================
extern "C" void kernel_launch(void* const* d_in, const int* in_sizes, int n_in,
                              void* d_out, int out_size)
{
    const float* X  = (const float*)d_in[0];
    const float* W1 = (const float*)d_in[1];
    const float* b1 = (const float*)d_in[2];
    const float* W2 = (const float*)d_in[3];
    const float* b2 = (const float*)d_in[4];
    const float* W3 = (const float*)d_in[5];
    const float* b3 = (const float*)d_in[6];
    const float* E  = (const float*)d_in[7];
    const float* W4 = (const float*)d_in[8];
    const float* b4 = (const float*)d_in[9];
    const float* W5 = (const float*)d_in[10];
    const float* b5 = (const float*)d_in[11];
    const float* W6 = (const float*)d_in[12];
    const float* b6 = (const float*)d_in[13];

    float* outf  = (float*)d_out;
    float* xrec  = outf + 1;
    float* q_out = outf + 1 + (size_t)B_SZ * GENE;

    __nv_bfloat16 *Xh, *Xm, *Xl, *W1h, *W1m, *W1l, *W2h, *W2m, *W2l;
    __nv_bfloat16 *h1h, *h1m, *h1l;
    __nv_bfloat16 *W4h, *W4l, *W5h, *W5l, *W6h, *W6l;
    __nv_bfloat16 *h4h, *h4l, *h5h, *h5l, *qh, *ql;
    float *h2f, *z, *S, *q, *enorm, *partial;
    int *idx;
    cudaGetSymbolAddress((void**)&Xh,  g_Xh);  cudaGetSymbolAddress((void**)&Xm,  g_Xm);
    cudaGetSymbolAddress((void**)&Xl,  g_Xl);
    cudaGetSymbolAddress((void**)&W1h, g_W1h); cudaGetSymbolAddress((void**)&W1m, g_W1m);
    cudaGetSymbolAddress((void**)&W1l, g_W1l);
    cudaGetSymbolAddress((void**)&W2h, g_W2h); cudaGetSymbolAddress((void**)&W2m, g_W2m);
    cudaGetSymbolAddress((void**)&W2l, g_W2l);
    cudaGetSymbolAddress((void**)&h1h, g_h1h); cudaGetSymbolAddress((void**)&h1m, g_h1m);
    cudaGetSymbolAddress((void**)&h1l, g_h1l);
    cudaGetSymbolAddress((void**)&W4h, g_W4h); cudaGetSymbolAddress((void**)&W4l, g_W4l);
    cudaGetSymbolAddress((void**)&W5h, g_W5h); cudaGetSymbolAddress((void**)&W5l, g_W5l);
    cudaGetSymbolAddress((void**)&W6h, g_W6h); cudaGetSymbolAddress((void**)&W6l, g_W6l);
    cudaGetSymbolAddress((void**)&h4h, g_h4h); cudaGetSymbolAddress((void**)&h4l, g_h4l);
    cudaGetSymbolAddress((void**)&h5h, g_h5h); cudaGetSymbolAddress((void**)&h5l, g_h5l);
    cudaGetSymbolAddress((void**)&qh,  g_qh);  cudaGetSymbolAddress((void**)&ql,  g_ql);
    cudaGetSymbolAddress((void**)&h2f, g_h2f);
    cudaGetSymbolAddress((void**)&z,   g_z);
    cudaGetSymbolAddress((void**)&S,   g_S);
    cudaGetSymbolAddress((void**)&q,   g_q);
    cudaGetSymbolAddress((void**)&enorm,   g_enorm);
    cudaGetSymbolAddress((void**)&partial, g_partial);
    cudaGetSymbolAddress((void**)&idx,     g_idx);

    cudaFuncSetAttribute(gemm_mma3_kernel<true,  false>,
                         cudaFuncAttributeMaxDynamicSharedMemorySize, SMEM_MMA3);
    cudaFuncSetAttribute(gemm_mma3_kernel<false, true>,
                         cudaFuncAttributeMaxDynamicSharedMemorySize, SMEM_MMA3);
    cudaFuncSetAttribute(gemm_mma2_kernel<true,  true,  false>,
                         cudaFuncAttributeMaxDynamicSharedMemorySize, SMEM_MMA2);
    cudaFuncSetAttribute(gemm_mma2_kernel<false, false, true>,
                         cudaFuncAttributeMaxDynamicSharedMemorySize, SMEM_MMA2);

    // ---- splits ----
    split3_kernel<<<4096, 256>>>((const float4*)X,  (__nv_bfloat162*)Xh,  (__nv_bfloat162*)Xm,  (__nv_bfloat162*)Xl,  (B_SZ * GENE) / 4);
    split3_kernel<<<4096, 256>>>((const float4*)W1, (__nv_bfloat162*)W1h, (__nv_bfloat162*)W1m, (__nv_bfloat162*)W1l, (D0 * GENE) / 4);
    split3_kernel<<<2048, 256>>>((const float4*)W2, (__nv_bfloat162*)W2h, (__nv_bfloat162*)W2m, (__nv_bfloat162*)W2l, (D1 * D0) / 4);
    split2_kernel<<<1024, 256>>>((const float4*)W4, (__nv_bfloat162*)W4h, (__nv_bfloat162*)W4l, (D1 * D2) / 4);
    split2_kernel<<<2048, 256>>>((const float4*)W5, (__nv_bfloat162*)W5h, (__nv_bfloat162*)W5l, (D0 * D1) / 4);
    split2_kernel<<<4096, 256>>>((const float4*)W6, (__nv_bfloat162*)W6h, (__nv_bfloat162*)W6l, (GENE * D0) / 4);
    enorm_kernel<<<NCODE, 128>>>(E, enorm);

    // ---- encoder (3-way split, 6 products, per-k-step flush) ----
    gemm_mma3_kernel<true, false><<<dim3(D0 / 128, B_SZ / 128), 256, SMEM_MMA3>>>(
        Xh, Xm, Xl, W1h, W1m, W1l, b1, h1h, h1m, h1l, (float*)nullptr, B_SZ, D0, GENE);
    gemm_mma3_kernel<false, true><<<dim3(D1 / 128, B_SZ / 128), 256, SMEM_MMA3>>>(
        h1h, h1m, h1l, W2h, W2m, W2l, b2,
        (__nv_bfloat16*)nullptr, (__nv_bfloat16*)nullptr, (__nv_bfloat16*)nullptr,
        h2f, B_SZ, D1, D0);

    // ---- VQ-critical path (fp32) ----
    gemm_nt_kernel<true, true><<<dim3(D2 / 128, B_SZ / 128), 256>>>(h2f, W3, b3, z, B_SZ, D2, D1);
    gemm_nt_kernel<false, false><<<dim3(NCODE / 128, B_SZ / 128), 256>>>(z, E, (const float*)nullptr, S, B_SZ, NCODE, D2);
    argmin_kernel<<<B_SZ, 256>>>(S, enorm, z, idx);
    gather_kernel<<<B_SZ, 128>>>(E, idx, q, q_out, qh, ql);
    loss_partial_kernel<<<B_SZ, 256>>>(q, z, partial);
    loss_final_kernel<<<1, 1024>>>(partial, outf);

    // ---- decoder (2-way split, 3 products) ----
    gemm_mma2_kernel<true, true, false><<<dim3(D1 / 128, B_SZ / 128), 256, SMEM_MMA2>>>(
        qh, ql, W4h, W4l, b4, h4h, h4l, (float*)nullptr, B_SZ, D1, D2);
    gemm_mma2_kernel<true, true, false><<<dim3(D0 / 128, B_SZ / 128), 256, SMEM_MMA2>>>(
        h4h, h4l, W5h, W5l, b5, h5h, h5l, (float*)nullptr, B_SZ, D0, D1);
    gemm_mma2_kernel<false, false, true><<<dim3(GENE / 128, B_SZ / 128), 256, SMEM_MMA2>>>(
        h5h, h5l, W6h, W6l, b6, (__nv_bfloat16*)nullptr, (__nv_bfloat16*)nullptr, xrec, B_SZ, GENE, D0);
}

// round 13
// speedup vs baseline: 1.7883x; 1.3240x over previous
#include <cuda_runtime.h>
#include <cuda_bf16.h>
#include <cuda_fp16.h>
#include <cstdint>
#include <math.h>

// ---------------------------------------------------------------------------
// VQ-VAE forward, round 9:
//   encoder G1,G2 : 2-way fp16 split (lo pre-scaled 2^10), 3 MMA products,
//                   per-k-step flush with scaled cross-term fold-in
//   decoder G4-G6 : 2-way bf16 split, 3 MMA products (verified)
//   VQ-critical   : fp32 SIMT (G3, z@E^T, fp32-rounding-emulated argmin)
// Output layout: [loss(1)][x_recon(B*G)][q_st(B*d2)]  (fp32)
// ---------------------------------------------------------------------------

#define B_SZ   4096
#define GENE   16384
#define D0     4096
#define D1     2048
#define D2     512
#define NCODE  8192

#define LO_SCALE     1024.0f
#define LO_INV_SCALE 0.0009765625f

// ============================ scratch =====================================
// encoder fp16 2-way
__device__ __align__(16) __half g_Xh [(size_t)B_SZ * GENE];
__device__ __align__(16) __half g_Xl [(size_t)B_SZ * GENE];
__device__ __align__(16) __half g_W1h[(size_t)D0 * GENE];
__device__ __align__(16) __half g_W1l[(size_t)D0 * GENE];
__device__ __align__(16) __half g_h1h[(size_t)B_SZ * D0];
__device__ __align__(16) __half g_h1l[(size_t)B_SZ * D0];
__device__ __align__(16) __half g_W2h[(size_t)D1 * D0];
__device__ __align__(16) __half g_W2l[(size_t)D1 * D0];
// decoder bf16 2-way
__device__ __align__(16) __nv_bfloat16 g_W4h[(size_t)D1 * D2];
__device__ __align__(16) __nv_bfloat16 g_W4l[(size_t)D1 * D2];
__device__ __align__(16) __nv_bfloat16 g_qh [(size_t)B_SZ * D2];
__device__ __align__(16) __nv_bfloat16 g_ql [(size_t)B_SZ * D2];
__device__ __align__(16) __nv_bfloat16 g_h4h[(size_t)B_SZ * D1];
__device__ __align__(16) __nv_bfloat16 g_h4l[(size_t)B_SZ * D1];
__device__ __align__(16) __nv_bfloat16 g_W5h[(size_t)D0 * D1];
__device__ __align__(16) __nv_bfloat16 g_W5l[(size_t)D0 * D1];
__device__ __align__(16) __nv_bfloat16 g_h5h[(size_t)B_SZ * D0];
__device__ __align__(16) __nv_bfloat16 g_h5l[(size_t)B_SZ * D0];
__device__ __align__(16) __nv_bfloat16 g_W6h[(size_t)GENE * D0];
__device__ __align__(16) __nv_bfloat16 g_W6l[(size_t)GENE * D0];
// fp32 path
__device__ float g_h2f[(size_t)B_SZ * D1];
__device__ float g_z  [(size_t)B_SZ * D2];
__device__ float g_S  [(size_t)B_SZ * NCODE];
__device__ float g_q  [(size_t)B_SZ * D2];
__device__ float g_enorm[NCODE];
__device__ float g_partial[B_SZ];
__device__ int   g_idx[B_SZ];

// ====================== split kernels =====================================
// fp32 -> bf16 hi/lo (decoder weights)
__global__ void split2_kernel(const float4* __restrict__ src,
                              __nv_bfloat162* __restrict__ hi,
                              __nv_bfloat162* __restrict__ lo, int n4)
{
    for (int i = blockIdx.x * blockDim.x + threadIdx.x; i < n4;
         i += gridDim.x * blockDim.x) {
        float4 v = src[i];
        float f[4] = { v.x, v.y, v.z, v.w };
        __nv_bfloat16 H[4], L[4];
#pragma unroll
        for (int j = 0; j < 4; j++) {
            H[j] = __float2bfloat16(f[j]);
            L[j] = __float2bfloat16(f[j] - __bfloat162float(H[j]));
        }
        hi[2 * i]     = __nv_bfloat162(H[0], H[1]);
        hi[2 * i + 1] = __nv_bfloat162(H[2], H[3]);
        lo[2 * i]     = __nv_bfloat162(L[0], L[1]);
        lo[2 * i + 1] = __nv_bfloat162(L[2], L[3]);
    }
}

// fp32 -> fp16 hi + (residual * 1024) lo  (encoder operands)
__global__ void split2h_kernel(const float4* __restrict__ src,
                               __half2* __restrict__ hi,
                               __half2* __restrict__ lo, int n4)
{
    for (int i = blockIdx.x * blockDim.x + threadIdx.x; i < n4;
         i += gridDim.x * blockDim.x) {
        float4 v = src[i];
        float f[4] = { v.x, v.y, v.z, v.w };
        __half H[4], L[4];
#pragma unroll
        for (int j = 0; j < 4; j++) {
            H[j] = __float2half_rn(f[j]);
            L[j] = __float2half_rn((f[j] - __half2float(H[j])) * LO_SCALE);
        }
        hi[2 * i]     = __half2(H[0], H[1]);
        hi[2 * i + 1] = __half2(H[2], H[3]);
        lo[2 * i]     = __half2(L[0], L[1]);
        lo[2 * i + 1] = __half2(L[2], L[3]);
    }
}

// ===================== mma.sync common pieces =============================
#define ROW_B    80
#define MAT_B    (128 * ROW_B)

__device__ __forceinline__ uint32_t smem_u32(const void* p) {
    uint32_t a;
    asm("{ .reg .u64 t; cvta.to.shared.u64 t, %1; cvt.u32.u64 %0, t; }"
        : "=r"(a) : "l"(p));
    return a;
}
__device__ __forceinline__ void ldmx4(uint32_t* r, uint32_t addr) {
    asm volatile("ldmatrix.sync.aligned.m8n8.x4.shared.b16 {%0,%1,%2,%3}, [%4];"
        : "=r"(r[0]), "=r"(r[1]), "=r"(r[2]), "=r"(r[3]) : "r"(addr));
}
__device__ __forceinline__ void mma16816_bf16(float* d, const uint32_t* a,
                                              uint32_t b0, uint32_t b1) {
    asm volatile(
        "mma.sync.aligned.m16n8k16.row.col.f32.bf16.bf16.f32 "
        "{%0,%1,%2,%3}, {%4,%5,%6,%7}, {%8,%9}, {%0,%1,%2,%3};"
        : "+f"(d[0]), "+f"(d[1]), "+f"(d[2]), "+f"(d[3])
        : "r"(a[0]), "r"(a[1]), "r"(a[2]), "r"(a[3]), "r"(b0), "r"(b1));
}
__device__ __forceinline__ void mma16816_f16(float* d, const uint32_t* a,
                                             uint32_t b0, uint32_t b1) {
    asm volatile(
        "mma.sync.aligned.m16n8k16.row.col.f32.f16.f16.f32 "
        "{%0,%1,%2,%3}, {%4,%5,%6,%7}, {%8,%9}, {%0,%1,%2,%3};"
        : "+f"(d[0]), "+f"(d[1]), "+f"(d[2]), "+f"(d[3])
        : "r"(a[0]), "r"(a[1]), "r"(a[2]), "r"(a[3]), "r"(b0), "r"(b1));
}

template<int NMAT, typename T>
__device__ __forceinline__ void load_stage_n(
    uint32_t st, const T* const* bases, int K, int k0, int tid)
{
#pragma unroll
    for (int i = 0; i < 2 * NMAT; i++) {
        int c   = tid + i * 256;
        int mat = c >> 9;
        int r   = (c & 511) >> 2;
        int ch  = c & 3;
        uint32_t dst = st + mat * MAT_B + r * ROW_B + ch * 16;
        const char* src = (const char*)bases[mat] + ((size_t)k0 + (size_t)r * K + ch * 8) * 2;
        asm volatile("cp.async.cg.shared.global [%0], [%1], 16;"
                     :: "r"(dst), "l"(src) : "memory");
    }
}

#define STAGE4_B  (4 * MAT_B)
#define NSTAGE4   4
#define SMEM_MMA4 (NSTAGE4 * STAGE4_B)   // 163840

// ============ 2-way bf16 GEMM (decoder): 3 products, plain accum ==========
template<bool TANH, bool WRITE_SPLIT, bool WRITE_F32>
__global__ __launch_bounds__(256, 1)
void gemm_mma2_kernel(const __nv_bfloat16* __restrict__ Ahi, const __nv_bfloat16* __restrict__ Alo,
                      const __nv_bfloat16* __restrict__ Bhi, const __nv_bfloat16* __restrict__ Blo,
                      const float* __restrict__ bias,
                      __nv_bfloat16* __restrict__ Chi, __nv_bfloat16* __restrict__ Clo,
                      float* __restrict__ Cf,
                      int M, int N, int K)
{
    extern __shared__ char smem[];
    const uint32_t sb = smem_u32(smem);
    const int tid = threadIdx.x;
    const int wid = tid >> 5;
    const int lid = tid & 31;
    const int wm  = wid >> 2;
    const int wn  = wid & 3;
    const int m0  = blockIdx.y * 128;
    const int n0  = blockIdx.x * 128;

    const __nv_bfloat16* bases[4] = {
        Ahi + (size_t)m0 * K, Alo + (size_t)m0 * K,
        Bhi + (size_t)n0 * K, Blo + (size_t)n0 * K };

    float acc[4][4][4];
#pragma unroll
    for (int i = 0; i < 4; i++)
#pragma unroll
        for (int j = 0; j < 4; j++)
#pragma unroll
            for (int v = 0; v < 4; v++) acc[i][j][v] = 0.0f;

    const int KT = K >> 5;
#pragma unroll
    for (int s = 0; s < NSTAGE4 - 1; s++) {
        if (s < KT) load_stage_n<4>(sb + s * STAGE4_B, bases, K, s << 5, tid);
        asm volatile("cp.async.commit_group;" ::: "memory");
    }

    const int lrow  = lid & 15;
    const int lhalf = lid >> 4;

    for (int kt = 0; kt < KT; kt++) {
        asm volatile("cp.async.wait_group %0;" :: "n"(NSTAGE4 - 2) : "memory");
        __syncthreads();

        const uint32_t st = sb + (kt % NSTAGE4) * STAGE4_B;
        const uint32_t a_base = st + (wm * 64 + lrow) * ROW_B + lhalf * 16;
        const uint32_t b_base = st + 2 * MAT_B + (wn * 32 + lrow) * ROW_B + lhalf * 16;

#pragma unroll
        for (int ks = 0; ks < 2; ks++) {
            uint32_t ah[4][4], al[4][4], bh[2][4], bl[2][4];
#pragma unroll
            for (int mi = 0; mi < 4; mi++) {
                ldmx4(ah[mi], a_base + mi * (16 * ROW_B) + ks * 32);
                ldmx4(al[mi], a_base + MAT_B + mi * (16 * ROW_B) + ks * 32);
            }
#pragma unroll
            for (int nj = 0; nj < 2; nj++) {
                ldmx4(bh[nj], b_base + nj * (16 * ROW_B) + ks * 32);
                ldmx4(bl[nj], b_base + MAT_B + nj * (16 * ROW_B) + ks * 32);
            }
#pragma unroll
            for (int mi = 0; mi < 4; mi++)
#pragma unroll
                for (int nj = 0; nj < 2; nj++)
#pragma unroll
                    for (int s = 0; s < 2; s++) {
                        float* d = acc[mi][nj * 2 + s];
                        mma16816_bf16(d, ah[mi], bh[nj][s], bh[nj][s + 2]);
                        mma16816_bf16(d, al[mi], bh[nj][s], bh[nj][s + 2]);
                        mma16816_bf16(d, ah[mi], bl[nj][s], bl[nj][s + 2]);
                    }
        }
        __syncthreads();

        const int nk = kt + NSTAGE4 - 1;
        if (nk < KT)
            load_stage_n<4>(sb + (nk % NSTAGE4) * STAGE4_B, bases, K, nk << 5, tid);
        asm volatile("cp.async.commit_group;" ::: "memory");
    }

    const int tr = lid >> 2;
    const int tc = (lid & 3) * 2;
#pragma unroll
    for (int mi = 0; mi < 4; mi++) {
#pragma unroll
        for (int nn = 0; nn < 4; nn++) {
            int n  = n0 + wn * 32 + nn * 8 + tc;
            float bv0 = bias[n], bv1 = bias[n + 1];
#pragma unroll
            for (int half = 0; half < 2; half++) {
                int m = m0 + wm * 64 + mi * 16 + tr + half * 8;
                float v0 = acc[mi][nn][half * 2 + 0] + bv0;
                float v1 = acc[mi][nn][half * 2 + 1] + bv1;
                if (TANH) { v0 = tanhf(v0); v1 = tanhf(v1); }
                size_t o = (size_t)m * N + n;
                if (WRITE_SPLIT) {
                    __nv_bfloat16 h0 = __float2bfloat16(v0);
                    __nv_bfloat16 h1 = __float2bfloat16(v1);
                    Chi[o]     = h0;
                    Chi[o + 1] = h1;
                    Clo[o]     = __float2bfloat16(v0 - __bfloat162float(h0));
                    Clo[o + 1] = __float2bfloat16(v1 - __bfloat162float(h1));
                }
                if (WRITE_F32) { Cf[o] = v0; Cf[o + 1] = v1; }
            }
        }
    }
}

// ==== 2-way fp16 GEMM (encoder): 3 products, per-k-step scaled flush ======
// lo operands pre-scaled by 2^10 (keeps residuals out of fp16 subnormals).
// Per k=16 step: HH into t_h, (LH + HL) into t_c (both zeroed), then
//   acc += t_h + t_c * 2^-10   (RN fma + add -> random-walk error, no drift)
template<bool WRITE_SPLITH, bool WRITE_F32>
__global__ __launch_bounds__(256, 1)
void gemm_mmaf16_kernel(const __half* __restrict__ Ahi, const __half* __restrict__ Alo,
                        const __half* __restrict__ Bhi, const __half* __restrict__ Blo,
                        const float* __restrict__ bias,
                        __half* __restrict__ Chi, __half* __restrict__ Clo,
                        float* __restrict__ Cf,
                        int M, int N, int K)
{
    extern __shared__ char smem[];
    const uint32_t sb = smem_u32(smem);
    const int tid = threadIdx.x;
    const int wid = tid >> 5;
    const int lid = tid & 31;
    const int wm  = wid >> 2;
    const int wn  = wid & 3;
    const int m0  = blockIdx.y * 128;
    const int n0  = blockIdx.x * 128;

    const __half* bases[4] = {
        Ahi + (size_t)m0 * K, Alo + (size_t)m0 * K,
        Bhi + (size_t)n0 * K, Blo + (size_t)n0 * K };

    float acc[4][4][4];
#pragma unroll
    for (int i = 0; i < 4; i++)
#pragma unroll
        for (int j = 0; j < 4; j++)
#pragma unroll
            for (int v = 0; v < 4; v++) acc[i][j][v] = 0.0f;

    const int KT = K >> 5;
#pragma unroll
    for (int s = 0; s < NSTAGE4 - 1; s++) {
        if (s < KT) load_stage_n<4>(sb + s * STAGE4_B, bases, K, s << 5, tid);
        asm volatile("cp.async.commit_group;" ::: "memory");
    }

    const int lrow  = lid & 15;
    const int lhalf = lid >> 4;

    for (int kt = 0; kt < KT; kt++) {
        asm volatile("cp.async.wait_group %0;" :: "n"(NSTAGE4 - 2) : "memory");
        __syncthreads();

        const uint32_t st = sb + (kt % NSTAGE4) * STAGE4_B;
        const uint32_t a_base = st + (wm * 64 + lrow) * ROW_B + lhalf * 16;
        const uint32_t b_base = st + 2 * MAT_B + (wn * 32 + lrow) * ROW_B + lhalf * 16;

#pragma unroll
        for (int ks = 0; ks < 2; ks++) {
            uint32_t ah[4][4], al[4][4], bh[2][4], bl[2][4];
#pragma unroll
            for (int mi = 0; mi < 4; mi++) {
                ldmx4(ah[mi], a_base + mi * (16 * ROW_B) + ks * 32);
                ldmx4(al[mi], a_base + MAT_B + mi * (16 * ROW_B) + ks * 32);
            }
#pragma unroll
            for (int nj = 0; nj < 2; nj++) {
                ldmx4(bh[nj], b_base + nj * (16 * ROW_B) + ks * 32);
                ldmx4(bl[nj], b_base + MAT_B + nj * (16 * ROW_B) + ks * 32);
            }
#pragma unroll
            for (int mi = 0; mi < 4; mi++)
#pragma unroll
                for (int nj = 0; nj < 2; nj++)
#pragma unroll
                    for (int s = 0; s < 2; s++) {
                        uint32_t h0 = bh[nj][s], h1 = bh[nj][s + 2];
                        float th[4] = {0.0f, 0.0f, 0.0f, 0.0f};
                        float tc[4] = {0.0f, 0.0f, 0.0f, 0.0f};
                        mma16816_f16(th, ah[mi], h0, h1);                       // HH
                        mma16816_f16(tc, al[mi], h0, h1);                       // LH (x2^10)
                        mma16816_f16(tc, ah[mi], bl[nj][s], bl[nj][s + 2]);     // HL (x2^10)
                        float* d = acc[mi][nj * 2 + s];
#pragma unroll
                        for (int v = 0; v < 4; v++)
                            d[v] = __fadd_rn(d[v], __fmaf_rn(tc[v], LO_INV_SCALE, th[v]));
                    }
        }
        __syncthreads();

        const int nk = kt + NSTAGE4 - 1;
        if (nk < KT)
            load_stage_n<4>(sb + (nk % NSTAGE4) * STAGE4_B, bases, K, nk << 5, tid);
        asm volatile("cp.async.commit_group;" ::: "memory");
    }

    const int tr = lid >> 2;
    const int tc2 = (lid & 3) * 2;
#pragma unroll
    for (int mi = 0; mi < 4; mi++) {
#pragma unroll
        for (int nn = 0; nn < 4; nn++) {
            int n  = n0 + wn * 32 + nn * 8 + tc2;
            float bv0 = bias[n], bv1 = bias[n + 1];
#pragma unroll
            for (int half = 0; half < 2; half++) {
                int m = m0 + wm * 64 + mi * 16 + tr + half * 8;
                float v0 = tanhf(acc[mi][nn][half * 2 + 0] + bv0);
                float v1 = tanhf(acc[mi][nn][half * 2 + 1] + bv1);
                size_t o = (size_t)m * N + n;
                if (WRITE_SPLITH) {
                    __half h0 = __float2half_rn(v0);
                    __half h1 = __float2half_rn(v1);
                    Chi[o]     = h0;
                    Chi[o + 1] = h1;
                    Clo[o]     = __float2half_rn((v0 - __half2float(h0)) * LO_SCALE);
                    Clo[o + 1] = __float2half_rn((v1 - __half2float(h1)) * LO_SCALE);
                }
                if (WRITE_F32) { Cf[o] = v0; Cf[o + 1] = v1; }
            }
        }
    }
}

// ===================== fp32 SIMT GEMM (VQ-critical path) ==================
template<bool TANH, bool BIAS>
__global__ __launch_bounds__(256, 2)
void gemm_nt_kernel(const float* __restrict__ A, const float* __restrict__ Bm,
                    const float* __restrict__ bias, float* __restrict__ C,
                    int M, int N, int K)
{
    __shared__ float As[16][128];
    __shared__ float Bs[16][128];
    const int tid = threadIdx.x;
    const int tx  = tid & 15;
    const int ty  = tid >> 4;
    const int m0  = blockIdx.y * 128;
    const int n0  = blockIdx.x * 128;

    float acc[8][8];
#pragma unroll
    for (int i = 0; i < 8; i++)
#pragma unroll
        for (int j = 0; j < 8; j++) acc[i][j] = 0.0f;

    for (int k0 = 0; k0 < K; k0 += 16) {
#pragma unroll
        for (int l = 0; l < 2; l++) {
            int fi = tid * 2 + l;
            int m = fi >> 2, kq = fi & 3;
            float4 v = *reinterpret_cast<const float4*>(&A[(size_t)(m0 + m) * K + k0 + kq * 4]);
            As[kq * 4 + 0][m] = v.x; As[kq * 4 + 1][m] = v.y;
            As[kq * 4 + 2][m] = v.z; As[kq * 4 + 3][m] = v.w;
        }
#pragma unroll
        for (int l = 0; l < 2; l++) {
            int fi = tid * 2 + l;
            int n = fi >> 2, kq = fi & 3;
            float4 v = *reinterpret_cast<const float4*>(&Bm[(size_t)(n0 + n) * K + k0 + kq * 4]);
            Bs[kq * 4 + 0][n] = v.x; Bs[kq * 4 + 1][n] = v.y;
            Bs[kq * 4 + 2][n] = v.z; Bs[kq * 4 + 3][n] = v.w;
        }
        __syncthreads();
#pragma unroll
        for (int kk = 0; kk < 16; kk++) {
            float a[8], b[8];
            *reinterpret_cast<float4*>(&a[0]) = *reinterpret_cast<float4*>(&As[kk][ty * 4]);
            *reinterpret_cast<float4*>(&a[4]) = *reinterpret_cast<float4*>(&As[kk][64 + ty * 4]);
            *reinterpret_cast<float4*>(&b[0]) = *reinterpret_cast<float4*>(&Bs[kk][tx * 4]);
            *reinterpret_cast<float4*>(&b[4]) = *reinterpret_cast<float4*>(&Bs[kk][64 + tx * 4]);
#pragma unroll
            for (int i = 0; i < 8; i++)
#pragma unroll
                for (int j = 0; j < 8; j++) acc[i][j] += a[i] * b[j];
        }
        __syncthreads();
    }
#pragma unroll
    for (int i = 0; i < 8; i++) {
        int m = m0 + ((i < 4) ? (ty * 4 + i) : (64 + ty * 4 + (i - 4)));
#pragma unroll
        for (int j = 0; j < 8; j++) {
            int n = n0 + ((j < 4) ? (tx * 4 + j) : (64 + tx * 4 + (j - 4)));
            float v = acc[i][j];
            if (BIAS) v += bias[n];
            if (TANH) v = tanhf(v);
            C[(size_t)m * N + n] = v;
        }
    }
}

// =========================== VQ helpers ===================================
__global__ void enorm_kernel(const float* __restrict__ E, float* __restrict__ enorm)
{
    int k = blockIdx.x;
    float s = 0.0f;
    for (int c = threadIdx.x; c < D2; c += 128) {
        float e = E[(size_t)k * D2 + c];
        s += e * e;
    }
    __shared__ float sh[128];
    sh[threadIdx.x] = s;
    __syncthreads();
    for (int off = 64; off > 0; off >>= 1) {
        if (threadIdx.x < off) sh[threadIdx.x] += sh[threadIdx.x + off];
        __syncthreads();
    }
    if (threadIdx.x == 0) enorm[k] = sh[0];
}

__global__ void argmin_kernel(const float* __restrict__ S,
                              const float* __restrict__ enorm,
                              const float* __restrict__ z,
                              int* __restrict__ idx)
{
    int row = blockIdx.x;
    const int t = threadIdx.x;
    __shared__ float sh[256];
    __shared__ float s_zz;
    {
        const float* zr = z + (size_t)row * D2;
        float a0 = zr[t], a1 = zr[t + 256];
        sh[t] = __fadd_rn(__fmul_rn(a0, a0), __fmul_rn(a1, a1));
        __syncthreads();
        for (int off = 128; off > 0; off >>= 1) {
            if (t < off) sh[t] = __fadd_rn(sh[t], sh[t + off]);
            __syncthreads();
        }
        if (t == 0) s_zz = sh[0];
        __syncthreads();
    }
    const float zz = s_zz;
    const float* s = S + (size_t)row * NCODE;
    float best = INFINITY;
    int   bi   = 0x7fffffff;
    for (int k = t; k < NCODE; k += 256) {
        float a = __fadd_rn(zz, enorm[k]);
        float y = __fmul_rn(2.0f, s[k]);
        float v = __fsub_rn(a, y);
        if (v < best || (v == best && k < bi)) { best = v; bi = k; }
    }
    __shared__ float sv[256];
    __shared__ int   si[256];
    sv[t] = best; si[t] = bi;
    __syncthreads();
    for (int off = 128; off > 0; off >>= 1) {
        if (t < off) {
            float v2 = sv[t + off]; int i2 = si[t + off];
            if (v2 < sv[t] || (v2 == sv[t] && i2 < si[t])) { sv[t] = v2; si[t] = i2; }
        }
        __syncthreads();
    }
    if (t == 0) idx[row] = si[0];
}

__global__ void gather_kernel(const float* __restrict__ E, const int* __restrict__ idx,
                              float* __restrict__ q_aligned, float* __restrict__ q_out,
                              __nv_bfloat16* __restrict__ qh, __nv_bfloat16* __restrict__ ql)
{
    int row = blockIdx.x;
    const float* src = E + (size_t)idx[row] * D2;
    size_t off = (size_t)row * D2;
    for (int c = threadIdx.x; c < D2; c += 128) {
        float v = src[c];
        q_aligned[off + c] = v;
        q_out[off + c]     = v;
        __nv_bfloat16 h = __float2bfloat16(v);
        qh[off + c] = h;
        ql[off + c] = __float2bfloat16(v - __bfloat162float(h));
    }
}

__global__ void loss_partial_kernel(const float* __restrict__ q, const float* __restrict__ z,
                                    float* __restrict__ partial)
{
    int row = blockIdx.x;
    float s = 0.0f;
    for (int c = threadIdx.x; c < D2; c += 256) {
        float d = q[(size_t)row * D2 + c] - z[(size_t)row * D2 + c];
        s += d * d;
    }
    __shared__ float sh[256];
    sh[threadIdx.x] = s;
    __syncthreads();
    for (int off = 128; off > 0; off >>= 1) {
        if (threadIdx.x < off) sh[threadIdx.x] += sh[threadIdx.x + off];
        __syncthreads();
    }
    if (threadIdx.x == 0) partial[row] = sh[0];
}

__global__ void loss_final_kernel(const float* __restrict__ partial, float* __restrict__ out)
{
    __shared__ float sh[1024];
    float s = 0.0f;
    for (int i = threadIdx.x; i < B_SZ; i += 1024) s += partial[i];
    sh[threadIdx.x] = s;
    __syncthreads();
    for (int off = 512; off > 0; off >>= 1) {
        if (threadIdx.x < off) sh[threadIdx.x] += sh[threadIdx.x + off];
        __syncthreads();
    }
    if (threadIdx.x == 0) out[0] = 1.25f * sh[0] / ((float)B_SZ * (float)D2);
}

// =============================== launch ===================================
extern "C" void kernel_launch(void* const* d_in, const int* in_sizes, int n_in,
                              void* d_out, int out_size)
{
    const float* X  = (const float*)d_in[0];
    const float* W1 = (const float*)d_in[1];
    const float* b1 = (const float*)d_in[2];
    const float* W2 = (const float*)d_in[3];
    const float* b2 = (const float*)d_in[4];
    const float* W3 = (const float*)d_in[5];
    const float* b3 = (const float*)d_in[6];
    const float* E  = (const float*)d_in[7];
    const float* W4 = (const float*)d_in[8];
    const float* b4 = (const float*)d_in[9];
    const float* W5 = (const float*)d_in[10];
    const float* b5 = (const float*)d_in[11];
    const float* W6 = (const float*)d_in[12];
    const float* b6 = (const float*)d_in[13];

    float* outf  = (float*)d_out;
    float* xrec  = outf + 1;
    float* q_out = outf + 1 + (size_t)B_SZ * GENE;

    __half *Xh, *Xl, *W1h, *W1l, *W2h, *W2l, *h1h, *h1l;
    __nv_bfloat16 *W4h, *W4l, *W5h, *W5l, *W6h, *W6l;
    __nv_bfloat16 *h4h, *h4l, *h5h, *h5l, *qh, *ql;
    float *h2f, *z, *S, *q, *enorm, *partial;
    int *idx;
    cudaGetSymbolAddress((void**)&Xh,  g_Xh);  cudaGetSymbolAddress((void**)&Xl,  g_Xl);
    cudaGetSymbolAddress((void**)&W1h, g_W1h); cudaGetSymbolAddress((void**)&W1l, g_W1l);
    cudaGetSymbolAddress((void**)&W2h, g_W2h); cudaGetSymbolAddress((void**)&W2l, g_W2l);
    cudaGetSymbolAddress((void**)&h1h, g_h1h); cudaGetSymbolAddress((void**)&h1l, g_h1l);
    cudaGetSymbolAddress((void**)&W4h, g_W4h); cudaGetSymbolAddress((void**)&W4l, g_W4l);
    cudaGetSymbolAddress((void**)&W5h, g_W5h); cudaGetSymbolAddress((void**)&W5l, g_W5l);
    cudaGetSymbolAddress((void**)&W6h, g_W6h); cudaGetSymbolAddress((void**)&W6l, g_W6l);
    cudaGetSymbolAddress((void**)&h4h, g_h4h); cudaGetSymbolAddress((void**)&h4l, g_h4l);
    cudaGetSymbolAddress((void**)&h5h, g_h5h); cudaGetSymbolAddress((void**)&h5l, g_h5l);
    cudaGetSymbolAddress((void**)&qh,  g_qh);  cudaGetSymbolAddress((void**)&ql,  g_ql);
    cudaGetSymbolAddress((void**)&h2f, g_h2f);
    cudaGetSymbolAddress((void**)&z,   g_z);
    cudaGetSymbolAddress((void**)&S,   g_S);
    cudaGetSymbolAddress((void**)&q,   g_q);
    cudaGetSymbolAddress((void**)&enorm,   g_enorm);
    cudaGetSymbolAddress((void**)&partial, g_partial);
    cudaGetSymbolAddress((void**)&idx,     g_idx);

    cudaFuncSetAttribute(gemm_mmaf16_kernel<true,  false>,
                         cudaFuncAttributeMaxDynamicSharedMemorySize, SMEM_MMA4);
    cudaFuncSetAttribute(gemm_mmaf16_kernel<false, true>,
                         cudaFuncAttributeMaxDynamicSharedMemorySize, SMEM_MMA4);
    cudaFuncSetAttribute(gemm_mma2_kernel<true,  true,  false>,
                         cudaFuncAttributeMaxDynamicSharedMemorySize, SMEM_MMA4);
    cudaFuncSetAttribute(gemm_mma2_kernel<false, false, true>,
                         cudaFuncAttributeMaxDynamicSharedMemorySize, SMEM_MMA4);

    // ---- splits ----
    split2h_kernel<<<4096, 256>>>((const float4*)X,  (__half2*)Xh,  (__half2*)Xl,  (B_SZ * GENE) / 4);
    split2h_kernel<<<4096, 256>>>((const float4*)W1, (__half2*)W1h, (__half2*)W1l, (D0 * GENE) / 4);
    split2h_kernel<<<2048, 256>>>((const float4*)W2, (__half2*)W2h, (__half2*)W2l, (D1 * D0) / 4);
    split2_kernel<<<1024, 256>>>((const float4*)W4, (__nv_bfloat162*)W4h, (__nv_bfloat162*)W4l, (D1 * D2) / 4);
    split2_kernel<<<2048, 256>>>((const float4*)W5, (__nv_bfloat162*)W5h, (__nv_bfloat162*)W5l, (D0 * D1) / 4);
    split2_kernel<<<4096, 256>>>((const float4*)W6, (__nv_bfloat162*)W6h, (__nv_bfloat162*)W6l, (GENE * D0) / 4);
    enorm_kernel<<<NCODE, 128>>>(E, enorm);

    // ---- encoder (fp16 2-way split, 3 products, per-k-step scaled flush) ----
    gemm_mmaf16_kernel<true, false><<<dim3(D0 / 128, B_SZ / 128), 256, SMEM_MMA4>>>(
        Xh, Xl, W1h, W1l, b1, h1h, h1l, (float*)nullptr, B_SZ, D0, GENE);
    gemm_mmaf16_kernel<false, true><<<dim3(D1 / 128, B_SZ / 128), 256, SMEM_MMA4>>>(
        h1h, h1l, W2h, W2l, b2, (__half*)nullptr, (__half*)nullptr, h2f, B_SZ, D1, D0);

    // ---- VQ-critical path (fp32) ----
    gemm_nt_kernel<true, true><<<dim3(D2 / 128, B_SZ / 128), 256>>>(h2f, W3, b3, z, B_SZ, D2, D1);
    gemm_nt_kernel<false, false><<<dim3(NCODE / 128, B_SZ / 128), 256>>>(z, E, (const float*)nullptr, S, B_SZ, NCODE, D2);
    argmin_kernel<<<B_SZ, 256>>>(S, enorm, z, idx);
    gather_kernel<<<B_SZ, 128>>>(E, idx, q, q_out, qh, ql);
    loss_partial_kernel<<<B_SZ, 256>>>(q, z, partial);
    loss_final_kernel<<<1, 1024>>>(partial, outf);

    // ---- decoder (bf16 2-way split, 3 products) ----
    gemm_mma2_kernel<true, true, false><<<dim3(D1 / 128, B_SZ / 128), 256, SMEM_MMA4>>>(
        qh, ql, W4h, W4l, b4, h4h, h4l, (float*)nullptr, B_SZ, D1, D2);
    gemm_mma2_kernel<true, true, false><<<dim3(D0 / 128, B_SZ / 128), 256, SMEM_MMA4>>>(
        h4h, h4l, W5h, W5l, b5, h5h, h5l, (float*)nullptr, B_SZ, D0, D1);
    gemm_mma2_kernel<false, false, true><<<dim3(GENE / 128, B_SZ / 128), 256, SMEM_MMA4>>>(
        h5h, h5l, W6h, W6l, b6, (__nv_bfloat16*)nullptr, (__nv_bfloat16*)nullptr, xrec, B_SZ, GENE, D0);
}

// round 14
// speedup vs baseline: 2.4955x; 1.3954x over previous
#include <cuda_runtime.h>
#include <cuda_bf16.h>
#include <cuda_fp16.h>
#include <cstdint>
#include <math.h>

// ---------------------------------------------------------------------------
// VQ-VAE forward, round 10:
//   encoder G1,G2 : 2-way fp16 split (lo x2^10), 3 MMA products, per-k flush
//   decoder G4-G6 : SINGLE-product fp16 HMMA (tolerance 1e-3, ~3e-4 predicted)
//   VQ-critical   : fp32 SIMT (G3, z@E^T, fp32-rounding-emulated argmin)
// Output layout: [loss(1)][x_recon(B*G)][q_st(B*d2)]  (fp32)
// ---------------------------------------------------------------------------

#define B_SZ   4096
#define GENE   16384
#define D0     4096
#define D1     2048
#define D2     512
#define NCODE  8192

#define LO_SCALE     1024.0f
#define LO_INV_SCALE 0.0009765625f

// ============================ scratch =====================================
// encoder fp16 2-way
__device__ __align__(16) __half g_Xh [(size_t)B_SZ * GENE];
__device__ __align__(16) __half g_Xl [(size_t)B_SZ * GENE];
__device__ __align__(16) __half g_W1h[(size_t)D0 * GENE];
__device__ __align__(16) __half g_W1l[(size_t)D0 * GENE];
__device__ __align__(16) __half g_h1h[(size_t)B_SZ * D0];
__device__ __align__(16) __half g_h1l[(size_t)B_SZ * D0];
__device__ __align__(16) __half g_W2h[(size_t)D1 * D0];
__device__ __align__(16) __half g_W2l[(size_t)D1 * D0];
// decoder single fp16
__device__ __align__(16) __half g_W4f[(size_t)D1 * D2];
__device__ __align__(16) __half g_W5f[(size_t)D0 * D1];
__device__ __align__(16) __half g_W6f[(size_t)GENE * D0];
__device__ __align__(16) __half g_qf [(size_t)B_SZ * D2];
__device__ __align__(16) __half g_h4f[(size_t)B_SZ * D1];
__device__ __align__(16) __half g_h5f[(size_t)B_SZ * D0];
// fp32 path
__device__ float g_h2f[(size_t)B_SZ * D1];
__device__ float g_z  [(size_t)B_SZ * D2];
__device__ float g_S  [(size_t)B_SZ * NCODE];
__device__ float g_q  [(size_t)B_SZ * D2];
__device__ float g_enorm[NCODE];
__device__ float g_partial[B_SZ];
__device__ int   g_idx[B_SZ];

// ====================== split / convert kernels ===========================
// fp32 -> fp16 hi + (residual * 1024) lo  (encoder operands)
__global__ void split2h_kernel(const float4* __restrict__ src,
                               __half2* __restrict__ hi,
                               __half2* __restrict__ lo, int n4)
{
    for (int i = blockIdx.x * blockDim.x + threadIdx.x; i < n4;
         i += gridDim.x * blockDim.x) {
        float4 v = src[i];
        float f[4] = { v.x, v.y, v.z, v.w };
        __half H[4], L[4];
#pragma unroll
        for (int j = 0; j < 4; j++) {
            H[j] = __float2half_rn(f[j]);
            L[j] = __float2half_rn((f[j] - __half2float(H[j])) * LO_SCALE);
        }
        hi[2 * i]     = __half2(H[0], H[1]);
        hi[2 * i + 1] = __half2(H[2], H[3]);
        lo[2 * i]     = __half2(L[0], L[1]);
        lo[2 * i + 1] = __half2(L[2], L[3]);
    }
}

// fp32 -> fp16 plain convert (decoder weights)
__global__ void cvt16_kernel(const float4* __restrict__ src,
                             __half2* __restrict__ dst, int n4)
{
    for (int i = blockIdx.x * blockDim.x + threadIdx.x; i < n4;
         i += gridDim.x * blockDim.x) {
        float4 v = src[i];
        dst[2 * i]     = __half2(__float2half_rn(v.x), __float2half_rn(v.y));
        dst[2 * i + 1] = __half2(__float2half_rn(v.z), __float2half_rn(v.w));
    }
}

// ===================== mma.sync common pieces =============================
#define ROW_B    80
#define MAT_B    (128 * ROW_B)

__device__ __forceinline__ uint32_t smem_u32(const void* p) {
    uint32_t a;
    asm("{ .reg .u64 t; cvta.to.shared.u64 t, %1; cvt.u32.u64 %0, t; }"
        : "=r"(a) : "l"(p));
    return a;
}
__device__ __forceinline__ void ldmx4(uint32_t* r, uint32_t addr) {
    asm volatile("ldmatrix.sync.aligned.m8n8.x4.shared.b16 {%0,%1,%2,%3}, [%4];"
        : "=r"(r[0]), "=r"(r[1]), "=r"(r[2]), "=r"(r[3]) : "r"(addr));
}
__device__ __forceinline__ void mma16816_f16(float* d, const uint32_t* a,
                                             uint32_t b0, uint32_t b1) {
    asm volatile(
        "mma.sync.aligned.m16n8k16.row.col.f32.f16.f16.f32 "
        "{%0,%1,%2,%3}, {%4,%5,%6,%7}, {%8,%9}, {%0,%1,%2,%3};"
        : "+f"(d[0]), "+f"(d[1]), "+f"(d[2]), "+f"(d[3])
        : "r"(a[0]), "r"(a[1]), "r"(a[2]), "r"(a[3]), "r"(b0), "r"(b1));
}

template<int NMAT, typename T>
__device__ __forceinline__ void load_stage_n(
    uint32_t st, const T* const* bases, int K, int k0, int tid)
{
#pragma unroll
    for (int i = 0; i < 2 * NMAT; i++) {
        int c   = tid + i * 256;
        int mat = c >> 9;
        int r   = (c & 511) >> 2;
        int ch  = c & 3;
        uint32_t dst = st + mat * MAT_B + r * ROW_B + ch * 16;
        const char* src = (const char*)bases[mat] + ((size_t)k0 + (size_t)r * K + ch * 8) * 2;
        asm volatile("cp.async.cg.shared.global [%0], [%1], 16;"
                     :: "r"(dst), "l"(src) : "memory");
    }
}

// ==== 2-way fp16 GEMM (encoder): 3 products, per-k-step scaled flush ======
#define STAGE4_B  (4 * MAT_B)
#define NSTAGE4   4
#define SMEM_MMA4 (NSTAGE4 * STAGE4_B)   // 163840

template<bool WRITE_SPLITH, bool WRITE_F32>
__global__ __launch_bounds__(256, 1)
void gemm_mmaf16_kernel(const __half* __restrict__ Ahi, const __half* __restrict__ Alo,
                        const __half* __restrict__ Bhi, const __half* __restrict__ Blo,
                        const float* __restrict__ bias,
                        __half* __restrict__ Chi, __half* __restrict__ Clo,
                        float* __restrict__ Cf,
                        int M, int N, int K)
{
    extern __shared__ char smem[];
    const uint32_t sb = smem_u32(smem);
    const int tid = threadIdx.x;
    const int wid = tid >> 5;
    const int lid = tid & 31;
    const int wm  = wid >> 2;
    const int wn  = wid & 3;
    const int m0  = blockIdx.y * 128;
    const int n0  = blockIdx.x * 128;

    const __half* bases[4] = {
        Ahi + (size_t)m0 * K, Alo + (size_t)m0 * K,
        Bhi + (size_t)n0 * K, Blo + (size_t)n0 * K };

    float acc[4][4][4];
#pragma unroll
    for (int i = 0; i < 4; i++)
#pragma unroll
        for (int j = 0; j < 4; j++)
#pragma unroll
            for (int v = 0; v < 4; v++) acc[i][j][v] = 0.0f;

    const int KT = K >> 5;
#pragma unroll
    for (int s = 0; s < NSTAGE4 - 1; s++) {
        if (s < KT) load_stage_n<4>(sb + s * STAGE4_B, bases, K, s << 5, tid);
        asm volatile("cp.async.commit_group;" ::: "memory");
    }

    const int lrow  = lid & 15;
    const int lhalf = lid >> 4;

    for (int kt = 0; kt < KT; kt++) {
        asm volatile("cp.async.wait_group %0;" :: "n"(NSTAGE4 - 2) : "memory");
        __syncthreads();

        const uint32_t st = sb + (kt % NSTAGE4) * STAGE4_B;
        const uint32_t a_base = st + (wm * 64 + lrow) * ROW_B + lhalf * 16;
        const uint32_t b_base = st + 2 * MAT_B + (wn * 32 + lrow) * ROW_B + lhalf * 16;

#pragma unroll
        for (int ks = 0; ks < 2; ks++) {
            uint32_t ah[4][4], al[4][4], bh[2][4], bl[2][4];
#pragma unroll
            for (int mi = 0; mi < 4; mi++) {
                ldmx4(ah[mi], a_base + mi * (16 * ROW_B) + ks * 32);
                ldmx4(al[mi], a_base + MAT_B + mi * (16 * ROW_B) + ks * 32);
            }
#pragma unroll
            for (int nj = 0; nj < 2; nj++) {
                ldmx4(bh[nj], b_base + nj * (16 * ROW_B) + ks * 32);
                ldmx4(bl[nj], b_base + MAT_B + nj * (16 * ROW_B) + ks * 32);
            }
#pragma unroll
            for (int mi = 0; mi < 4; mi++)
#pragma unroll
                for (int nj = 0; nj < 2; nj++)
#pragma unroll
                    for (int s = 0; s < 2; s++) {
                        uint32_t h0 = bh[nj][s], h1 = bh[nj][s + 2];
                        float th[4] = {0.0f, 0.0f, 0.0f, 0.0f};
                        float tc[4] = {0.0f, 0.0f, 0.0f, 0.0f};
                        mma16816_f16(th, ah[mi], h0, h1);                       // HH
                        mma16816_f16(tc, al[mi], h0, h1);                       // LH (x2^10)
                        mma16816_f16(tc, ah[mi], bl[nj][s], bl[nj][s + 2]);     // HL (x2^10)
                        float* d = acc[mi][nj * 2 + s];
#pragma unroll
                        for (int v = 0; v < 4; v++)
                            d[v] = __fadd_rn(d[v], __fmaf_rn(tc[v], LO_INV_SCALE, th[v]));
                    }
        }
        __syncthreads();

        const int nk = kt + NSTAGE4 - 1;
        if (nk < KT)
            load_stage_n<4>(sb + (nk % NSTAGE4) * STAGE4_B, bases, K, nk << 5, tid);
        asm volatile("cp.async.commit_group;" ::: "memory");
    }

    const int tr = lid >> 2;
    const int tc2 = (lid & 3) * 2;
#pragma unroll
    for (int mi = 0; mi < 4; mi++) {
#pragma unroll
        for (int nn = 0; nn < 4; nn++) {
            int n  = n0 + wn * 32 + nn * 8 + tc2;
            float bv0 = bias[n], bv1 = bias[n + 1];
#pragma unroll
            for (int half = 0; half < 2; half++) {
                int m = m0 + wm * 64 + mi * 16 + tr + half * 8;
                float v0 = tanhf(acc[mi][nn][half * 2 + 0] + bv0);
                float v1 = tanhf(acc[mi][nn][half * 2 + 1] + bv1);
                size_t o = (size_t)m * N + n;
                if (WRITE_SPLITH) {
                    __half h0 = __float2half_rn(v0);
                    __half h1 = __float2half_rn(v1);
                    Chi[o]     = h0;
                    Chi[o + 1] = h1;
                    Clo[o]     = __float2half_rn((v0 - __half2float(h0)) * LO_SCALE);
                    Clo[o + 1] = __float2half_rn((v1 - __half2float(h1)) * LO_SCALE);
                }
                if (WRITE_F32) { Cf[o] = v0; Cf[o + 1] = v1; }
            }
        }
    }
}

// ===== single-product fp16 GEMM (decoder): plain accumulation, 5 stages ====
#define STAGE1_B  (2 * MAT_B)            // 20480
#define NSTAGE1   5
#define SMEM_MMA1 (NSTAGE1 * STAGE1_B)   // 102400

template<bool TANH, bool WRITE_F16, bool WRITE_F32>
__global__ __launch_bounds__(256, 1)
void gemm_f16s_kernel(const __half* __restrict__ A, const __half* __restrict__ B,
                      const float* __restrict__ bias,
                      __half* __restrict__ C16, float* __restrict__ Cf,
                      int M, int N, int K)
{
    extern __shared__ char smem[];
    const uint32_t sb = smem_u32(smem);
    const int tid = threadIdx.x;
    const int wid = tid >> 5;
    const int lid = tid & 31;
    const int wm  = wid >> 2;
    const int wn  = wid & 3;
    const int m0  = blockIdx.y * 128;
    const int n0  = blockIdx.x * 128;

    const __half* bases[2] = { A + (size_t)m0 * K, B + (size_t)n0 * K };

    float acc[4][4][4];
#pragma unroll
    for (int i = 0; i < 4; i++)
#pragma unroll
        for (int j = 0; j < 4; j++)
#pragma unroll
            for (int v = 0; v < 4; v++) acc[i][j][v] = 0.0f;

    const int KT = K >> 5;
#pragma unroll
    for (int s = 0; s < NSTAGE1 - 1; s++) {
        if (s < KT) load_stage_n<2>(sb + s * STAGE1_B, bases, K, s << 5, tid);
        asm volatile("cp.async.commit_group;" ::: "memory");
    }

    const int lrow  = lid & 15;
    const int lhalf = lid >> 4;

    for (int kt = 0; kt < KT; kt++) {
        asm volatile("cp.async.wait_group %0;" :: "n"(NSTAGE1 - 2) : "memory");
        __syncthreads();

        const uint32_t st = sb + (kt % NSTAGE1) * STAGE1_B;
        const uint32_t a_base = st + (wm * 64 + lrow) * ROW_B + lhalf * 16;
        const uint32_t b_base = st + MAT_B + (wn * 32 + lrow) * ROW_B + lhalf * 16;

#pragma unroll
        for (int ks = 0; ks < 2; ks++) {
            uint32_t af[4][4], bf[2][4];
#pragma unroll
            for (int mi = 0; mi < 4; mi++)
                ldmx4(af[mi], a_base + mi * (16 * ROW_B) + ks * 32);
#pragma unroll
            for (int nj = 0; nj < 2; nj++)
                ldmx4(bf[nj], b_base + nj * (16 * ROW_B) + ks * 32);
#pragma unroll
            for (int mi = 0; mi < 4; mi++)
#pragma unroll
                for (int nj = 0; nj < 2; nj++)
#pragma unroll
                    for (int s = 0; s < 2; s++)
                        mma16816_f16(acc[mi][nj * 2 + s], af[mi], bf[nj][s], bf[nj][s + 2]);
        }
        __syncthreads();

        const int nk = kt + NSTAGE1 - 1;
        if (nk < KT)
            load_stage_n<2>(sb + (nk % NSTAGE1) * STAGE1_B, bases, K, nk << 5, tid);
        asm volatile("cp.async.commit_group;" ::: "memory");
    }

    const int tr = lid >> 2;
    const int tc = (lid & 3) * 2;
#pragma unroll
    for (int mi = 0; mi < 4; mi++) {
#pragma unroll
        for (int nn = 0; nn < 4; nn++) {
            int n  = n0 + wn * 32 + nn * 8 + tc;
            float bv0 = bias[n], bv1 = bias[n + 1];
#pragma unroll
            for (int half = 0; half < 2; half++) {
                int m = m0 + wm * 64 + mi * 16 + tr + half * 8;
                float v0 = acc[mi][nn][half * 2 + 0] + bv0;
                float v1 = acc[mi][nn][half * 2 + 1] + bv1;
                if (TANH) { v0 = tanhf(v0); v1 = tanhf(v1); }
                size_t o = (size_t)m * N + n;
                if (WRITE_F16) {
                    C16[o]     = __float2half_rn(v0);
                    C16[o + 1] = __float2half_rn(v1);
                }
                if (WRITE_F32) { Cf[o] = v0; Cf[o + 1] = v1; }
            }
        }
    }
}

// ===================== fp32 SIMT GEMM (VQ-critical path) ==================
template<bool TANH, bool BIAS>
__global__ __launch_bounds__(256, 2)
void gemm_nt_kernel(const float* __restrict__ A, const float* __restrict__ Bm,
                    const float* __restrict__ bias, float* __restrict__ C,
                    int M, int N, int K)
{
    __shared__ float As[16][128];
    __shared__ float Bs[16][128];
    const int tid = threadIdx.x;
    const int tx  = tid & 15;
    const int ty  = tid >> 4;
    const int m0  = blockIdx.y * 128;
    const int n0  = blockIdx.x * 128;

    float acc[8][8];
#pragma unroll
    for (int i = 0; i < 8; i++)
#pragma unroll
        for (int j = 0; j < 8; j++) acc[i][j] = 0.0f;

    for (int k0 = 0; k0 < K; k0 += 16) {
#pragma unroll
        for (int l = 0; l < 2; l++) {
            int fi = tid * 2 + l;
            int m = fi >> 2, kq = fi & 3;
            float4 v = *reinterpret_cast<const float4*>(&A[(size_t)(m0 + m) * K + k0 + kq * 4]);
            As[kq * 4 + 0][m] = v.x; As[kq * 4 + 1][m] = v.y;
            As[kq * 4 + 2][m] = v.z; As[kq * 4 + 3][m] = v.w;
        }
#pragma unroll
        for (int l = 0; l < 2; l++) {
            int fi = tid * 2 + l;
            int n = fi >> 2, kq = fi & 3;
            float4 v = *reinterpret_cast<const float4*>(&Bm[(size_t)(n0 + n) * K + k0 + kq * 4]);
            Bs[kq * 4 + 0][n] = v.x; Bs[kq * 4 + 1][n] = v.y;
            Bs[kq * 4 + 2][n] = v.z; Bs[kq * 4 + 3][n] = v.w;
        }
        __syncthreads();
#pragma unroll
        for (int kk = 0; kk < 16; kk++) {
            float a[8], b[8];
            *reinterpret_cast<float4*>(&a[0]) = *reinterpret_cast<float4*>(&As[kk][ty * 4]);
            *reinterpret_cast<float4*>(&a[4]) = *reinterpret_cast<float4*>(&As[kk][64 + ty * 4]);
            *reinterpret_cast<float4*>(&b[0]) = *reinterpret_cast<float4*>(&Bs[kk][tx * 4]);
            *reinterpret_cast<float4*>(&b[4]) = *reinterpret_cast<float4*>(&Bs[kk][64 + tx * 4]);
#pragma unroll
            for (int i = 0; i < 8; i++)
#pragma unroll
                for (int j = 0; j < 8; j++) acc[i][j] += a[i] * b[j];
        }
        __syncthreads();
    }
#pragma unroll
    for (int i = 0; i < 8; i++) {
        int m = m0 + ((i < 4) ? (ty * 4 + i) : (64 + ty * 4 + (i - 4)));
#pragma unroll
        for (int j = 0; j < 8; j++) {
            int n = n0 + ((j < 4) ? (tx * 4 + j) : (64 + tx * 4 + (j - 4)));
            float v = acc[i][j];
            if (BIAS) v += bias[n];
            if (TANH) v = tanhf(v);
            C[(size_t)m * N + n] = v;
        }
    }
}

// =========================== VQ helpers ===================================
__global__ void enorm_kernel(const float* __restrict__ E, float* __restrict__ enorm)
{
    int k = blockIdx.x;
    float s = 0.0f;
    for (int c = threadIdx.x; c < D2; c += 128) {
        float e = E[(size_t)k * D2 + c];
        s += e * e;
    }
    __shared__ float sh[128];
    sh[threadIdx.x] = s;
    __syncthreads();
    for (int off = 64; off > 0; off >>= 1) {
        if (threadIdx.x < off) sh[threadIdx.x] += sh[threadIdx.x + off];
        __syncthreads();
    }
    if (threadIdx.x == 0) enorm[k] = sh[0];
}

__global__ void argmin_kernel(const float* __restrict__ S,
                              const float* __restrict__ enorm,
                              const float* __restrict__ z,
                              int* __restrict__ idx)
{
    int row = blockIdx.x;
    const int t = threadIdx.x;
    __shared__ float sh[256];
    __shared__ float s_zz;
    {
        const float* zr = z + (size_t)row * D2;
        float a0 = zr[t], a1 = zr[t + 256];
        sh[t] = __fadd_rn(__fmul_rn(a0, a0), __fmul_rn(a1, a1));
        __syncthreads();
        for (int off = 128; off > 0; off >>= 1) {
            if (t < off) sh[t] = __fadd_rn(sh[t], sh[t + off]);
            __syncthreads();
        }
        if (t == 0) s_zz = sh[0];
        __syncthreads();
    }
    const float zz = s_zz;
    const float* s = S + (size_t)row * NCODE;
    float best = INFINITY;
    int   bi   = 0x7fffffff;
    for (int k = t; k < NCODE; k += 256) {
        float a = __fadd_rn(zz, enorm[k]);
        float y = __fmul_rn(2.0f, s[k]);
        float v = __fsub_rn(a, y);
        if (v < best || (v == best && k < bi)) { best = v; bi = k; }
    }
    __shared__ float sv[256];
    __shared__ int   si[256];
    sv[t] = best; si[t] = bi;
    __syncthreads();
    for (int off = 128; off > 0; off >>= 1) {
        if (t < off) {
            float v2 = sv[t + off]; int i2 = si[t + off];
            if (v2 < sv[t] || (v2 == sv[t] && i2 < si[t])) { sv[t] = v2; si[t] = i2; }
        }
        __syncthreads();
    }
    if (t == 0) idx[row] = si[0];
}

__global__ void gather_kernel(const float* __restrict__ E, const int* __restrict__ idx,
                              float* __restrict__ q_aligned, float* __restrict__ q_out,
                              __half* __restrict__ qf)
{
    int row = blockIdx.x;
    const float* src = E + (size_t)idx[row] * D2;
    size_t off = (size_t)row * D2;
    for (int c = threadIdx.x; c < D2; c += 128) {
        float v = src[c];
        q_aligned[off + c] = v;
        q_out[off + c]     = v;
        qf[off + c]        = __float2half_rn(v);
    }
}

__global__ void loss_partial_kernel(const float* __restrict__ q, const float* __restrict__ z,
                                    float* __restrict__ partial)
{
    int row = blockIdx.x;
    float s = 0.0f;
    for (int c = threadIdx.x; c < D2; c += 256) {
        float d = q[(size_t)row * D2 + c] - z[(size_t)row * D2 + c];
        s += d * d;
    }
    __shared__ float sh[256];
    sh[threadIdx.x] = s;
    __syncthreads();
    for (int off = 128; off > 0; off >>= 1) {
        if (threadIdx.x < off) sh[threadIdx.x] += sh[threadIdx.x + off];
        __syncthreads();
    }
    if (threadIdx.x == 0) partial[row] = sh[0];
}

__global__ void loss_final_kernel(const float* __restrict__ partial, float* __restrict__ out)
{
    __shared__ float sh[1024];
    float s = 0.0f;
    for (int i = threadIdx.x; i < B_SZ; i += 1024) s += partial[i];
    sh[threadIdx.x] = s;
    __syncthreads();
    for (int off = 512; off > 0; off >>= 1) {
        if (threadIdx.x < off) sh[threadIdx.x] += sh[threadIdx.x + off];
        __syncthreads();
    }
    if (threadIdx.x == 0) out[0] = 1.25f * sh[0] / ((float)B_SZ * (float)D2);
}

// =============================== launch ===================================
extern "C" void kernel_launch(void* const* d_in, const int* in_sizes, int n_in,
                              void* d_out, int out_size)
{
    const float* X  = (const float*)d_in[0];
    const float* W1 = (const float*)d_in[1];
    const float* b1 = (const float*)d_in[2];
    const float* W2 = (const float*)d_in[3];
    const float* b2 = (const float*)d_in[4];
    const float* W3 = (const float*)d_in[5];
    const float* b3 = (const float*)d_in[6];
    const float* E  = (const float*)d_in[7];
    const float* W4 = (const float*)d_in[8];
    const float* b4 = (const float*)d_in[9];
    const float* W5 = (const float*)d_in[10];
    const float* b5 = (const float*)d_in[11];
    const float* W6 = (const float*)d_in[12];
    const float* b6 = (const float*)d_in[13];

    float* outf  = (float*)d_out;
    float* xrec  = outf + 1;
    float* q_out = outf + 1 + (size_t)B_SZ * GENE;

    __half *Xh, *Xl, *W1h, *W1l, *W2h, *W2l, *h1h, *h1l;
    __half *W4f, *W5f, *W6f, *qf, *h4f, *h5f;
    float *h2f, *z, *S, *q, *enorm, *partial;
    int *idx;
    cudaGetSymbolAddress((void**)&Xh,  g_Xh);  cudaGetSymbolAddress((void**)&Xl,  g_Xl);
    cudaGetSymbolAddress((void**)&W1h, g_W1h); cudaGetSymbolAddress((void**)&W1l, g_W1l);
    cudaGetSymbolAddress((void**)&W2h, g_W2h); cudaGetSymbolAddress((void**)&W2l, g_W2l);
    cudaGetSymbolAddress((void**)&h1h, g_h1h); cudaGetSymbolAddress((void**)&h1l, g_h1l);
    cudaGetSymbolAddress((void**)&W4f, g_W4f);
    cudaGetSymbolAddress((void**)&W5f, g_W5f);
    cudaGetSymbolAddress((void**)&W6f, g_W6f);
    cudaGetSymbolAddress((void**)&qf,  g_qf);
    cudaGetSymbolAddress((void**)&h4f, g_h4f);
    cudaGetSymbolAddress((void**)&h5f, g_h5f);
    cudaGetSymbolAddress((void**)&h2f, g_h2f);
    cudaGetSymbolAddress((void**)&z,   g_z);
    cudaGetSymbolAddress((void**)&S,   g_S);
    cudaGetSymbolAddress((void**)&q,   g_q);
    cudaGetSymbolAddress((void**)&enorm,   g_enorm);
    cudaGetSymbolAddress((void**)&partial, g_partial);
    cudaGetSymbolAddress((void**)&idx,     g_idx);

    cudaFuncSetAttribute(gemm_mmaf16_kernel<true,  false>,
                         cudaFuncAttributeMaxDynamicSharedMemorySize, SMEM_MMA4);
    cudaFuncSetAttribute(gemm_mmaf16_kernel<false, true>,
                         cudaFuncAttributeMaxDynamicSharedMemorySize, SMEM_MMA4);
    cudaFuncSetAttribute(gemm_f16s_kernel<true,  true,  false>,
                         cudaFuncAttributeMaxDynamicSharedMemorySize, SMEM_MMA1);
    cudaFuncSetAttribute(gemm_f16s_kernel<false, false, true>,
                         cudaFuncAttributeMaxDynamicSharedMemorySize, SMEM_MMA1);

    // ---- splits / converts (one element per thread: full HBM rate) ----
    split2h_kernel<<<65536, 256>>>((const float4*)X,  (__half2*)Xh,  (__half2*)Xl,  (B_SZ * GENE) / 4);
    split2h_kernel<<<65536, 256>>>((const float4*)W1, (__half2*)W1h, (__half2*)W1l, (D0 * GENE) / 4);
    split2h_kernel<<<8192,  256>>>((const float4*)W2, (__half2*)W2h, (__half2*)W2l, (D1 * D0) / 4);
    cvt16_kernel<<<1024,  256>>>((const float4*)W4, (__half2*)W4f, (D1 * D2) / 4);
    cvt16_kernel<<<8192,  256>>>((const float4*)W5, (__half2*)W5f, (D0 * D1) / 4);
    cvt16_kernel<<<65536, 256>>>((const float4*)W6, (__half2*)W6f, (GENE * D0) / 4);
    enorm_kernel<<<NCODE, 128>>>(E, enorm);

    // ---- encoder (fp16 2-way split, 3 products, per-k-step scaled flush) ----
    gemm_mmaf16_kernel<true, false><<<dim3(D0 / 128, B_SZ / 128), 256, SMEM_MMA4>>>(
        Xh, Xl, W1h, W1l, b1, h1h, h1l, (float*)nullptr, B_SZ, D0, GENE);
    gemm_mmaf16_kernel<false, true><<<dim3(D1 / 128, B_SZ / 128), 256, SMEM_MMA4>>>(
        h1h, h1l, W2h, W2l, b2, (__half*)nullptr, (__half*)nullptr, h2f, B_SZ, D1, D0);

    // ---- VQ-critical path (fp32) ----
    gemm_nt_kernel<true, true><<<dim3(D2 / 128, B_SZ / 128), 256>>>(h2f, W3, b3, z, B_SZ, D2, D1);
    gemm_nt_kernel<false, false><<<dim3(NCODE / 128, B_SZ / 128), 256>>>(z, E, (const float*)nullptr, S, B_SZ, NCODE, D2);
    argmin_kernel<<<B_SZ, 256>>>(S, enorm, z, idx);
    gather_kernel<<<B_SZ, 128>>>(E, idx, q, q_out, qf);
    loss_partial_kernel<<<B_SZ, 256>>>(q, z, partial);
    loss_final_kernel<<<1, 1024>>>(partial, outf);

    // ---- decoder (single-product fp16) ----
    gemm_f16s_kernel<true, true, false><<<dim3(D1 / 128, B_SZ / 128), 256, SMEM_MMA1>>>(
        qf, W4f, b4, h4f, (float*)nullptr, B_SZ, D1, D2);
    gemm_f16s_kernel<true, true, false><<<dim3(D0 / 128, B_SZ / 128), 256, SMEM_MMA1>>>(
        h4f, W5f, b5, h5f, (float*)nullptr, B_SZ, D0, D1);
    gemm_f16s_kernel<false, false, true><<<dim3(GENE / 128, B_SZ / 128), 256, SMEM_MMA1>>>(
        h5f, W6f, b6, (__half*)nullptr, xrec, B_SZ, GENE, D0);
}